// round 1
// baseline (speedup 1.0000x reference)
#include <cuda_runtime.h>
#include <math.h>

// Problem constants
#define NB    4
#define TSEQ  1024
#define CDIM  1024
#define NH    16
#define DH    64
#define MROWS (NB * TSEQ)      // 4096
#define KDIM  1024

// Scratch (device globals -- no allocation allowed)
__device__ float g_Q[(size_t)NB * NH * TSEQ * DH];
__device__ float g_K[(size_t)NB * NH * TSEQ * DH];
__device__ float g_V[(size_t)NB * NH * TSEQ * DH];
__device__ float g_Y[(size_t)MROWS * CDIM];

// ---------------------------------------------------------------------------
// Tiled SGEMM: out[m][n] = sum_k X[m][k] * W[k][n] + bias[n]
// MODE 0: QKV -> scatter into g_Q/g_K/g_V as [b,h,t,d]
// MODE 1: proj -> X is g_Y (internal), write d_out [m][n]
// BM=BN=128, BK=16, 256 threads, 8x8 micro-tile per thread.
// ---------------------------------------------------------------------------
template <int N, int MODE>
__global__ __launch_bounds__(256) void sgemm_kernel(
    const float* __restrict__ X, const float* __restrict__ W,
    const float* __restrict__ bias, float* __restrict__ out)
{
    __shared__ float As[16 * 128];   // transposed: As[k][m]
    __shared__ float Bs[16 * 128];   // Bs[k][n]

    const int bm = blockIdx.y * 128;
    const int bn = blockIdx.x * 128;
    const int tid = threadIdx.x;
    const int tx = tid & 15;
    const int ty = tid >> 4;

    const float* Xp = (MODE == 0) ? X : g_Y;

    float acc[8][8];
#pragma unroll
    for (int i = 0; i < 8; i++)
#pragma unroll
        for (int j = 0; j < 8; j++) acc[i][j] = 0.0f;

    for (int k0 = 0; k0 < KDIM; k0 += 16) {
#pragma unroll
        for (int l = 0; l < 2; l++) {
            int idx = tid + l * 256;            // 0..511
            // A tile: 128 rows x 16 k, float4 along k
            int row = idx >> 2;
            int kq  = idx & 3;
            float4 a = *(const float4*)(Xp + (size_t)(bm + row) * KDIM + k0 + kq * 4);
            As[(kq * 4 + 0) * 128 + row] = a.x;
            As[(kq * 4 + 1) * 128 + row] = a.y;
            As[(kq * 4 + 2) * 128 + row] = a.z;
            As[(kq * 4 + 3) * 128 + row] = a.w;
            // B tile: 16 rows x 128 n, float4 along n
            int krow = idx >> 5;                // 0..15
            int nq   = idx & 31;                // 0..31
            *(float4*)(Bs + krow * 128 + nq * 4) =
                *(const float4*)(W + (size_t)(k0 + krow) * N + bn + nq * 4);
        }
        __syncthreads();

#pragma unroll
        for (int k = 0; k < 16; k++) {
            float4 a0 = *(const float4*)(As + k * 128 + ty * 8);
            float4 a1 = *(const float4*)(As + k * 128 + ty * 8 + 4);
            float4 b0 = *(const float4*)(Bs + k * 128 + tx * 8);
            float4 b1 = *(const float4*)(Bs + k * 128 + tx * 8 + 4);
            float av[8] = {a0.x, a0.y, a0.z, a0.w, a1.x, a1.y, a1.z, a1.w};
            float bv[8] = {b0.x, b0.y, b0.z, b0.w, b1.x, b1.y, b1.z, b1.w};
#pragma unroll
            for (int i = 0; i < 8; i++)
#pragma unroll
                for (int j = 0; j < 8; j++)
                    acc[i][j] += av[i] * bv[j];
        }
        __syncthreads();
    }

    // Epilogue
#pragma unroll
    for (int i = 0; i < 8; i++) {
        int m = bm + ty * 8 + i;
#pragma unroll
        for (int j = 0; j < 8; j++) {
            int n = bn + tx * 8 + j;
            float v = acc[i][j] + bias[n];
            if (MODE == 0) {
                int sec  = n >> 10;       // 0=q, 1=k, 2=v
                int col  = n & 1023;
                int head = col >> 6;
                int dpos = col & 63;
                int b = m >> 10;
                int t = m & 1023;
                size_t dst = ((size_t)((b * NH + head) * TSEQ + t)) * DH + dpos;
                float* base = (sec == 0) ? g_Q : ((sec == 1) ? g_K : g_V);
                base[dst] = v;
            } else {
                out[(size_t)m * N + n] = v;
            }
        }
    }
}

// ---------------------------------------------------------------------------
// Flash attention (fp32, online softmax, causal).
// Grid: (T/64 q-tiles, B*H). Block: 256 threads = 8 warps; warp w owns query
// rows w*8..w*8+7 of the tile; lane owns key-cols {lane, lane+32} for S/P and
// d-cols {lane, lane+32} for O.
// ---------------------------------------------------------------------------
#define SPAD 68   // 64 + 4 pad: float4-aligned, conflict-free

__global__ __launch_bounds__(256) void attn_kernel()
{
    extern __shared__ float sm[];
    float* Qs = sm;                    // [64][SPAD]
    float* Ks = Qs + 64 * SPAD;
    float* Vs = Ks + 64 * SPAD;
    float* Ps = Vs + 64 * SPAD;

    const int qi = blockIdx.x;         // q tile index (0..15)
    const int bh = blockIdx.y;         // b*NH + h
    const int bb = bh >> 4;
    const int hh = bh & 15;

    const float* Qb = g_Q + (size_t)bh * TSEQ * DH;
    const float* Kb = g_K + (size_t)bh * TSEQ * DH;
    const float* Vb = g_V + (size_t)bh * TSEQ * DH;

    const int tid  = threadIdx.x;
    const int warp = tid >> 5;
    const int lane = tid & 31;
    const int c0 = lane, c1 = lane + 32;

    // Load Q tile
    for (int i = tid; i < 64 * 64; i += 256) {
        int r = i >> 6, d = i & 63;
        Qs[r * SPAD + d] = Qb[(size_t)(qi * 64 + r) * DH + d];
    }

    float o0[8], o1[8], mrow[8], lrow[8];
#pragma unroll
    for (int r = 0; r < 8; r++) {
        o0[r] = 0.0f; o1[r] = 0.0f;
        mrow[r] = -INFINITY; lrow[r] = 0.0f;
    }

    const float scale = 0.125f;  // 1/sqrt(64)

    for (int j = 0; j <= qi; j++) {
        __syncthreads();   // previous tile fully consumed (also fences Q load on j=0)
        for (int i = tid; i < 64 * 64; i += 256) {
            int r = i >> 6, d = i & 63;
            Ks[r * SPAD + d] = Kb[(size_t)(j * 64 + r) * DH + d];
            Vs[r * SPAD + d] = Vb[(size_t)(j * 64 + r) * DH + d];
        }
        __syncthreads();

        // S = Q @ K^T (warp rows x 64 cols; lane covers c0,c1)
        float s0[8], s1[8];
#pragma unroll
        for (int r = 0; r < 8; r++) { s0[r] = 0.0f; s1[r] = 0.0f; }
#pragma unroll
        for (int d4 = 0; d4 < 16; d4++) {
            float4 k0 = *(const float4*)(Ks + c0 * SPAD + d4 * 4);
            float4 k1 = *(const float4*)(Ks + c1 * SPAD + d4 * 4);
#pragma unroll
            for (int r = 0; r < 8; r++) {
                float4 q = *(const float4*)(Qs + (warp * 8 + r) * SPAD + d4 * 4);
                s0[r] += q.x * k0.x + q.y * k0.y + q.z * k0.z + q.w * k0.w;
                s1[r] += q.x * k1.x + q.y * k1.y + q.z * k1.z + q.w * k1.w;
            }
        }

        const bool diag = (j == qi);
#pragma unroll
        for (int r = 0; r < 8; r++) {
            float v0 = s0[r] * scale;
            float v1 = s1[r] * scale;
            if (diag) {
                int qg = warp * 8 + r;     // local row == local causal bound
                if (c0 > qg) v0 = -INFINITY;
                if (c1 > qg) v1 = -INFINITY;
            }
            float mt = fmaxf(v0, v1);
#pragma unroll
            for (int off = 16; off > 0; off >>= 1)
                mt = fmaxf(mt, __shfl_xor_sync(0xffffffffu, mt, off));
            float mnew = fmaxf(mrow[r], mt);
            float p0 = __expf(v0 - mnew);
            float p1 = __expf(v1 - mnew);
            float ps = p0 + p1;
#pragma unroll
            for (int off = 16; off > 0; off >>= 1)
                ps += __shfl_xor_sync(0xffffffffu, ps, off);
            float alpha = __expf(mrow[r] - mnew);   // 0 on first tile (-inf - finite)
            lrow[r] = lrow[r] * alpha + ps;
            mrow[r] = mnew;
            o0[r] *= alpha;
            o1[r] *= alpha;
            Ps[(warp * 8 + r) * SPAD + c0] = p0;
            Ps[(warp * 8 + r) * SPAD + c1] = p1;
        }
        __syncwarp();   // P is warp-private (own rows only)

        // O += P @ V  (lane covers d = lane, lane+32)
#pragma unroll
        for (int c4 = 0; c4 < 16; c4++) {
            float va0 = Vs[(c4 * 4 + 0) * SPAD + lane];
            float va1 = Vs[(c4 * 4 + 1) * SPAD + lane];
            float va2 = Vs[(c4 * 4 + 2) * SPAD + lane];
            float va3 = Vs[(c4 * 4 + 3) * SPAD + lane];
            float vb0 = Vs[(c4 * 4 + 0) * SPAD + lane + 32];
            float vb1 = Vs[(c4 * 4 + 1) * SPAD + lane + 32];
            float vb2 = Vs[(c4 * 4 + 2) * SPAD + lane + 32];
            float vb3 = Vs[(c4 * 4 + 3) * SPAD + lane + 32];
#pragma unroll
            for (int r = 0; r < 8; r++) {
                float4 p = *(const float4*)(Ps + (warp * 8 + r) * SPAD + c4 * 4);
                o0[r] += p.x * va0 + p.y * va1 + p.z * va2 + p.w * va3;
                o1[r] += p.x * vb0 + p.y * vb1 + p.z * vb2 + p.w * vb3;
            }
        }
    }

    // Normalize and write y as [b][t][c] with c = h*64 + d
#pragma unroll
    for (int r = 0; r < 8; r++) {
        float inv = 1.0f / lrow[r];
        int t = qi * 64 + warp * 8 + r;
        size_t base = ((size_t)bb * TSEQ + t) * CDIM + hh * DH;
        g_Y[base + lane]      = o0[r] * inv;
        g_Y[base + lane + 32] = o1[r] * inv;
    }
}

// ---------------------------------------------------------------------------
// Launch
// ---------------------------------------------------------------------------
extern "C" void kernel_launch(void* const* d_in, const int* in_sizes, int n_in,
                              void* d_out, int out_size)
{
    const float* x      = (const float*)d_in[0];
    const float* w_attn = (const float*)d_in[1];
    const float* b_attn = (const float*)d_in[2];
    const float* w_proj = (const float*)d_in[3];
    const float* b_proj = (const float*)d_in[4];
    float* out = (float*)d_out;

    // 1) QKV GEMM + scatter to [b,h,t,d]
    {
        dim3 grid(3 * CDIM / 128, MROWS / 128);   // (24, 32)
        sgemm_kernel<3 * CDIM, 0><<<grid, 256>>>(x, w_attn, b_attn, nullptr);
    }

    // 2) Flash attention
    {
        size_t smem = (size_t)4 * 64 * SPAD * sizeof(float);   // 69632 B
        cudaFuncSetAttribute(attn_kernel,
                             cudaFuncAttributeMaxDynamicSharedMemorySize,
                             (int)smem);
        dim3 grid(TSEQ / 64, NB * NH);            // (16, 64)
        attn_kernel<<<grid, 256, smem>>>();
    }

    // 3) Output projection
    {
        dim3 grid(CDIM / 128, MROWS / 128);       // (8, 32)
        sgemm_kernel<CDIM, 1><<<grid, 256>>>(nullptr, w_proj, b_proj, out);
    }
}

// round 4
// speedup vs baseline: 1.3247x; 1.3247x over previous
#include <cuda_runtime.h>
#include <math.h>
#include <stdint.h>

// Problem constants
#define NB    4
#define TSEQ  1024
#define CDIM  1024
#define NH    16
#define DH    64
#define MROWS (NB * TSEQ)      // 4096
#define KDIM  1024

// Scratch (device globals -- no allocation allowed)
__device__ float g_Q[(size_t)NB * NH * TSEQ * DH];
__device__ float g_K[(size_t)NB * NH * TSEQ * DH];
__device__ float g_V[(size_t)NB * NH * TSEQ * DH];
__device__ float g_Y[(size_t)MROWS * CDIM];
__device__ float g_Wt[(size_t)3 * CDIM * KDIM];    // w_attn transposed: [n][k]
__device__ float g_WtP[(size_t)CDIM * KDIM];       // w_proj transposed: [n][k]

// ---------------------------------------------------------------------------
// Helpers
// ---------------------------------------------------------------------------
__device__ __forceinline__ uint32_t smem_u32(const void* p) {
    return (uint32_t)__cvta_generic_to_shared(p);
}

__device__ __forceinline__ void cp_async16(uint32_t saddr, const void* gptr) {
    asm volatile("cp.async.cg.shared.global [%0], [%1], 16;" :: "r"(saddr), "l"(gptr));
}
#define CP_COMMIT() asm volatile("cp.async.commit_group;" ::: "memory")

__device__ __forceinline__ void ldsm_x4(uint32_t* r, uint32_t addr) {
    asm volatile("ldmatrix.sync.aligned.m8n8.x4.shared.b16 {%0,%1,%2,%3}, [%4];"
                 : "=r"(r[0]), "=r"(r[1]), "=r"(r[2]), "=r"(r[3]) : "r"(addr));
}

__device__ __forceinline__ void mma_tf32(float* c, const uint32_t* a,
                                         uint32_t b0, uint32_t b1) {
    asm volatile(
        "mma.sync.aligned.m16n8k8.row.col.f32.tf32.tf32.f32 "
        "{%0,%1,%2,%3}, {%4,%5,%6,%7}, {%8,%9}, {%0,%1,%2,%3};"
        : "+f"(c[0]), "+f"(c[1]), "+f"(c[2]), "+f"(c[3])
        : "r"(a[0]), "r"(a[1]), "r"(a[2]), "r"(a[3]), "r"(b0), "r"(b1));
}

__device__ __forceinline__ uint32_t to_tf32(float f) {
    uint32_t r;
    asm("cvt.rna.tf32.f32 %0, %1;" : "=r"(r) : "f"(f));
    return r;
}

// Split fp32 bit-pattern x into tf32 hi + tf32 lo (residual)
__device__ __forceinline__ void split_tf32(uint32_t x, uint32_t& hi, uint32_t& lo) {
    float f = __uint_as_float(x);
    hi = to_tf32(f);
    lo = to_tf32(f - __uint_as_float(hi));
}

// ---------------------------------------------------------------------------
// Weight transpose: src [KDIM rows][cols] -> dst [cols][KDIM]
// ---------------------------------------------------------------------------
template <int WHICH>
__global__ __launch_bounds__(256) void transpose_kernel(const float* __restrict__ src, int cols)
{
    __shared__ float tile[32][33];
    float* dst = WHICH ? g_WtP : g_Wt;
    const int c0 = blockIdx.x * 32;
    const int r0 = blockIdx.y * 32;
    const int tx = threadIdx.x, ty = threadIdx.y;   // (32, 8)
#pragma unroll
    for (int j = 0; j < 32; j += 8)
        tile[ty + j][tx] = src[(size_t)(r0 + ty + j) * cols + c0 + tx];
    __syncthreads();
#pragma unroll
    for (int j = 0; j < 32; j += 8)
        dst[(size_t)(c0 + ty + j) * KDIM + r0 + tx] = tile[tx][ty + j];
}

// ---------------------------------------------------------------------------
// 3xTF32 mma.sync GEMM: out[m][n] = sum_k A[m][k] * B[n][k] + bias[n]
// A: MODE0 -> x; MODE1 -> g_Y.  B: MODE0 -> g_Wt; MODE1 -> g_WtP (both [n][k]).
// BM=BN=128, BK=32, 4-stage cp.async, 8 warps (4m x 2n), warp tile 32x64.
// Per fragment: split into tf32 hi/lo; acc += al*bh + ah*bl + ah*bh.
// MODE0 scatters into g_Q/g_K/g_V as [b,h,t,d]; MODE1 writes out[m][n].
// ---------------------------------------------------------------------------
#define GBM 128
#define GBN 128
#define GBK 32
#define NST 4
#define KTILES   (KDIM / GBK)           // 32
#define STAGE_B  (GBM * GBK * 4)        // 16384 bytes per matrix per stage
#define GSMEM    (2 * NST * STAGE_B)    // 131072

__device__ __forceinline__ void load_tile(uint32_t sA, uint32_t sB,
                                          const float* Ag, const float* Bg,
                                          int k0, int tid)
{
#pragma unroll
    for (int l = 0; l < 4; l++) {
        int idx = tid + l * 256;          // 0..1023
        int row = idx >> 3;               // 0..127
        int q   = idx & 7;                // 16B chunk along k
        uint32_t off = row * 128 + q * 16;
        uint32_t sw  = off ^ ((off >> 3) & 0x70);
        cp_async16(sA + sw, Ag + (size_t)row * KDIM + k0 + q * 4);
        cp_async16(sB + sw, Bg + (size_t)row * KDIM + k0 + q * 4);
    }
}

template <int N, int MODE>
__global__ __launch_bounds__(256) void tc_gemm(const float* __restrict__ Xin,
                                               const float* __restrict__ bias,
                                               float* __restrict__ out)
{
    extern __shared__ char smem[];
    const uint32_t sbase = smem_u32(smem);
    const int tid  = threadIdx.x;
    const int warp = tid >> 5;
    const int lane = tid & 31;
    const int wm = warp >> 1;             // 0..3
    const int wn = warp & 1;              // 0..1
    const int bm = blockIdx.y * GBM;
    const int bn = blockIdx.x * GBN;

    const float* A = ((MODE == 0) ? Xin : g_Y) + (size_t)bm * KDIM;
    const float* B = ((MODE == 0) ? g_Wt : g_WtP) + (size_t)bn * KDIM;

    // ldmatrix lane-address precompute
    const int arow = wm * 32 + (lane & 15);                 // + mi*16
    const uint32_t a_rowoff = (uint32_t)arow * 128;
    const int a_rx = arow & 7;
    const int acb = (lane >> 4) & 1;
    const int brow = wn * 64 + (lane & 7) + ((lane & 16) >> 1);  // + pi*16
    const uint32_t b_rowoff = (uint32_t)brow * 128;
    const int b_rx = brow & 7;
    const int bcb = (lane >> 3) & 1;

    float acc[2][8][4];
#pragma unroll
    for (int mi = 0; mi < 2; mi++)
#pragma unroll
        for (int ni = 0; ni < 8; ni++)
#pragma unroll
            for (int r = 0; r < 4; r++) acc[mi][ni][r] = 0.0f;

    // Prologue: prefetch stages 0..2
#pragma unroll
    for (int t = 0; t < 3; t++) {
        load_tile(sbase + t * STAGE_B, sbase + (NST + t) * STAGE_B, A, B, t * GBK, tid);
        CP_COMMIT();
    }

    for (int t = 0; t < KTILES; t++) {
        if (t < KTILES - 2)
            asm volatile("cp.async.wait_group 2;" ::: "memory");
        else if (t == KTILES - 2)
            asm volatile("cp.async.wait_group 1;" ::: "memory");
        else
            asm volatile("cp.async.wait_group 0;" ::: "memory");
        __syncthreads();

        const uint32_t sA = sbase + (t & 3) * STAGE_B;
        const uint32_t sB = sbase + (NST + (t & 3)) * STAGE_B;

#pragma unroll
        for (int ks = 0; ks < 4; ks++) {
            uint32_t a[2][4], b[4][4];
#pragma unroll
            for (int mi = 0; mi < 2; mi++)
                ldsm_x4(a[mi], sA + a_rowoff + mi * 2048 +
                               (uint32_t)(((ks * 2 + acb) ^ a_rx) << 4));
#pragma unroll
            for (int pi = 0; pi < 4; pi++)
                ldsm_x4(b[pi], sB + b_rowoff + pi * 2048 +
                               (uint32_t)(((ks * 2 + bcb) ^ b_rx) << 4));

            // 3xTF32 split
            uint32_t ah[2][4], al[2][4], bh[4][4], bl[4][4];
#pragma unroll
            for (int mi = 0; mi < 2; mi++)
#pragma unroll
                for (int j = 0; j < 4; j++)
                    split_tf32(a[mi][j], ah[mi][j], al[mi][j]);
#pragma unroll
            for (int pi = 0; pi < 4; pi++)
#pragma unroll
                for (int j = 0; j < 4; j++)
                    split_tf32(b[pi][j], bh[pi][j], bl[pi][j]);

#pragma unroll
            for (int mi = 0; mi < 2; mi++)
#pragma unroll
                for (int ni = 0; ni < 8; ni++) {
                    const int pi = ni >> 1;
                    const int j0 = (ni & 1) * 2;
                    // small terms first, then dominant
                    mma_tf32(acc[mi][ni], al[mi], bh[pi][j0], bh[pi][j0 + 1]);
                    mma_tf32(acc[mi][ni], ah[mi], bl[pi][j0], bl[pi][j0 + 1]);
                    mma_tf32(acc[mi][ni], ah[mi], bh[pi][j0], bh[pi][j0 + 1]);
                }
        }

        if (t + 3 < KTILES) {
            const int tn = t + 3;
            load_tile(sbase + (tn & 3) * STAGE_B, sbase + (NST + (tn & 3)) * STAGE_B,
                      A, B, tn * GBK, tid);
            CP_COMMIT();
        }
    }

    // Epilogue
#pragma unroll
    for (int mi = 0; mi < 2; mi++) {
#pragma unroll
        for (int ni = 0; ni < 8; ni++) {
            const int col = bn + wn * 64 + ni * 8 + (lane & 3) * 2;
            float2 bv = *(const float2*)(bias + col);
#pragma unroll
            for (int half = 0; half < 2; half++) {
                const int row = bm + wm * 32 + mi * 16 + (lane >> 2) + half * 8;
                float2 v;
                v.x = acc[mi][ni][half * 2 + 0] + bv.x;
                v.y = acc[mi][ni][half * 2 + 1] + bv.y;
                if (MODE == 0) {
                    const int sec  = col >> 10;          // 0=q, 1=k, 2=v
                    const int cc   = col & 1023;
                    const int head = cc >> 6;
                    const int dpos = cc & 63;
                    const int b  = row >> 10;
                    const int tt = row & 1023;
                    float* basep = (sec == 0) ? g_Q : ((sec == 1) ? g_K : g_V);
                    *(float2*)(basep + (((size_t)(b * NH + head) * TSEQ + tt) * DH + dpos)) = v;
                } else {
                    *(float2*)(out + (size_t)row * N + col) = v;
                }
            }
        }
    }
}

// ---------------------------------------------------------------------------
// Flash attention (fp32, online softmax, causal) -- unchanged
// ---------------------------------------------------------------------------
#define SPAD 68

__global__ __launch_bounds__(256) void attn_kernel()
{
    extern __shared__ float sm[];
    float* Qs = sm;
    float* Ks = Qs + 64 * SPAD;
    float* Vs = Ks + 64 * SPAD;
    float* Ps = Vs + 64 * SPAD;

    const int qi = blockIdx.x;
    const int bh = blockIdx.y;
    const int bb = bh >> 4;
    const int hh = bh & 15;

    const float* Qb = g_Q + (size_t)bh * TSEQ * DH;
    const float* Kb = g_K + (size_t)bh * TSEQ * DH;
    const float* Vb = g_V + (size_t)bh * TSEQ * DH;

    const int tid  = threadIdx.x;
    const int warp = tid >> 5;
    const int lane = tid & 31;
    const int c0 = lane, c1 = lane + 32;

    for (int i = tid; i < 64 * 64; i += 256) {
        int r = i >> 6, d = i & 63;
        Qs[r * SPAD + d] = Qb[(size_t)(qi * 64 + r) * DH + d];
    }

    float o0[8], o1[8], mrow[8], lrow[8];
#pragma unroll
    for (int r = 0; r < 8; r++) {
        o0[r] = 0.0f; o1[r] = 0.0f;
        mrow[r] = -INFINITY; lrow[r] = 0.0f;
    }

    const float scale = 0.125f;

    for (int j = 0; j <= qi; j++) {
        __syncthreads();
        for (int i = tid; i < 64 * 64; i += 256) {
            int r = i >> 6, d = i & 63;
            Ks[r * SPAD + d] = Kb[(size_t)(j * 64 + r) * DH + d];
            Vs[r * SPAD + d] = Vb[(size_t)(j * 64 + r) * DH + d];
        }
        __syncthreads();

        float s0[8], s1[8];
#pragma unroll
        for (int r = 0; r < 8; r++) { s0[r] = 0.0f; s1[r] = 0.0f; }
#pragma unroll
        for (int d4 = 0; d4 < 16; d4++) {
            float4 k0 = *(const float4*)(Ks + c0 * SPAD + d4 * 4);
            float4 k1 = *(const float4*)(Ks + c1 * SPAD + d4 * 4);
#pragma unroll
            for (int r = 0; r < 8; r++) {
                float4 q = *(const float4*)(Qs + (warp * 8 + r) * SPAD + d4 * 4);
                s0[r] += q.x * k0.x + q.y * k0.y + q.z * k0.z + q.w * k0.w;
                s1[r] += q.x * k1.x + q.y * k1.y + q.z * k1.z + q.w * k1.w;
            }
        }

        const bool diag = (j == qi);
#pragma unroll
        for (int r = 0; r < 8; r++) {
            float v0 = s0[r] * scale;
            float v1 = s1[r] * scale;
            if (diag) {
                int qg = warp * 8 + r;
                if (c0 > qg) v0 = -INFINITY;
                if (c1 > qg) v1 = -INFINITY;
            }
            float mt = fmaxf(v0, v1);
#pragma unroll
            for (int off = 16; off > 0; off >>= 1)
                mt = fmaxf(mt, __shfl_xor_sync(0xffffffffu, mt, off));
            float mnew = fmaxf(mrow[r], mt);
            float p0 = __expf(v0 - mnew);
            float p1 = __expf(v1 - mnew);
            float ps = p0 + p1;
#pragma unroll
            for (int off = 16; off > 0; off >>= 1)
                ps += __shfl_xor_sync(0xffffffffu, ps, off);
            float alpha = __expf(mrow[r] - mnew);
            lrow[r] = lrow[r] * alpha + ps;
            mrow[r] = mnew;
            o0[r] *= alpha;
            o1[r] *= alpha;
            Ps[(warp * 8 + r) * SPAD + c0] = p0;
            Ps[(warp * 8 + r) * SPAD + c1] = p1;
        }
        __syncwarp();

#pragma unroll
        for (int c4 = 0; c4 < 16; c4++) {
            float va0 = Vs[(c4 * 4 + 0) * SPAD + lane];
            float va1 = Vs[(c4 * 4 + 1) * SPAD + lane];
            float va2 = Vs[(c4 * 4 + 2) * SPAD + lane];
            float va3 = Vs[(c4 * 4 + 3) * SPAD + lane];
            float vb0 = Vs[(c4 * 4 + 0) * SPAD + lane + 32];
            float vb1 = Vs[(c4 * 4 + 1) * SPAD + lane + 32];
            float vb2 = Vs[(c4 * 4 + 2) * SPAD + lane + 32];
            float vb3 = Vs[(c4 * 4 + 3) * SPAD + lane + 32];
#pragma unroll
            for (int r = 0; r < 8; r++) {
                float4 p = *(const float4*)(Ps + (warp * 8 + r) * SPAD + c4 * 4);
                o0[r] += p.x * va0 + p.y * va1 + p.z * va2 + p.w * va3;
                o1[r] += p.x * vb0 + p.y * vb1 + p.z * vb2 + p.w * vb3;
            }
        }
    }

#pragma unroll
    for (int r = 0; r < 8; r++) {
        float inv = 1.0f / lrow[r];
        int t = qi * 64 + warp * 8 + r;
        size_t base = ((size_t)bb * TSEQ + t) * CDIM + hh * DH;
        g_Y[base + lane]      = o0[r] * inv;
        g_Y[base + lane + 32] = o1[r] * inv;
    }
}

// ---------------------------------------------------------------------------
// Launch
// ---------------------------------------------------------------------------
extern "C" void kernel_launch(void* const* d_in, const int* in_sizes, int n_in,
                              void* d_out, int out_size)
{
    const float* x      = (const float*)d_in[0];
    const float* w_attn = (const float*)d_in[1];
    const float* b_attn = (const float*)d_in[2];
    const float* w_proj = (const float*)d_in[3];
    const float* b_proj = (const float*)d_in[4];
    float* out = (float*)d_out;

    // 0) Transpose weights to [n][k]
    {
        dim3 blk(32, 8);
        transpose_kernel<0><<<dim3(3 * CDIM / 32, KDIM / 32), blk>>>(w_attn, 3 * CDIM);
        transpose_kernel<1><<<dim3(CDIM / 32, KDIM / 32), blk>>>(w_proj, CDIM);
    }

    // 1) QKV GEMM (3xtf32 mma.sync) + scatter to [b,h,t,d]
    {
        cudaFuncSetAttribute(tc_gemm<3 * CDIM, 0>,
                             cudaFuncAttributeMaxDynamicSharedMemorySize, GSMEM);
        dim3 grid(3 * CDIM / GBN, MROWS / GBM);   // (24, 32)
        tc_gemm<3 * CDIM, 0><<<grid, 256, GSMEM>>>(x, b_attn, nullptr);
    }

    // 2) Flash attention
    {
        size_t smem = (size_t)4 * 64 * SPAD * sizeof(float);
        cudaFuncSetAttribute(attn_kernel,
                             cudaFuncAttributeMaxDynamicSharedMemorySize, (int)smem);
        dim3 grid(TSEQ / 64, NB * NH);            // (16, 64)
        attn_kernel<<<grid, 256, smem>>>();
    }

    // 3) Output projection (3xtf32 mma.sync)
    {
        cudaFuncSetAttribute(tc_gemm<CDIM, 1>,
                             cudaFuncAttributeMaxDynamicSharedMemorySize, GSMEM);
        dim3 grid(CDIM / GBN, MROWS / GBM);       // (8, 32)
        tc_gemm<CDIM, 1><<<grid, 256, GSMEM>>>(nullptr, b_proj, out);
    }
}

// round 5
// speedup vs baseline: 1.5520x; 1.1716x over previous
#include <cuda_runtime.h>
#include <math.h>
#include <stdint.h>

// Problem constants
#define NB    4
#define TSEQ  1024
#define CDIM  1024
#define NH    16
#define DH    64
#define MROWS (NB * TSEQ)      // 4096
#define KDIM  1024

// Scratch (device globals -- no allocation allowed)
__device__ float g_Q[(size_t)NB * NH * TSEQ * DH];
__device__ float g_K[(size_t)NB * NH * TSEQ * DH];
__device__ float g_V[(size_t)NB * NH * TSEQ * DH];
__device__ float g_Y[(size_t)MROWS * CDIM];
__device__ float g_Wt[(size_t)3 * CDIM * KDIM];    // w_attn transposed: [n][k]
__device__ float g_WtP[(size_t)CDIM * KDIM];       // w_proj transposed: [n][k]

// ---------------------------------------------------------------------------
// Helpers
// ---------------------------------------------------------------------------
__device__ __forceinline__ uint32_t smem_u32(const void* p) {
    return (uint32_t)__cvta_generic_to_shared(p);
}

__device__ __forceinline__ void cp_async16(uint32_t saddr, const void* gptr) {
    asm volatile("cp.async.cg.shared.global [%0], [%1], 16;" :: "r"(saddr), "l"(gptr));
}
#define CP_COMMIT() asm volatile("cp.async.commit_group;" ::: "memory")

__device__ __forceinline__ void ldsm_x4(uint32_t* r, uint32_t addr) {
    asm volatile("ldmatrix.sync.aligned.m8n8.x4.shared.b16 {%0,%1,%2,%3}, [%4];"
                 : "=r"(r[0]), "=r"(r[1]), "=r"(r[2]), "=r"(r[3]) : "r"(addr));
}

__device__ __forceinline__ void mma_tf32(float* c, const uint32_t* a,
                                         uint32_t b0, uint32_t b1) {
    asm volatile(
        "mma.sync.aligned.m16n8k8.row.col.f32.tf32.tf32.f32 "
        "{%0,%1,%2,%3}, {%4,%5,%6,%7}, {%8,%9}, {%0,%1,%2,%3};"
        : "+f"(c[0]), "+f"(c[1]), "+f"(c[2]), "+f"(c[3])
        : "r"(a[0]), "r"(a[1]), "r"(a[2]), "r"(a[3]), "r"(b0), "r"(b1));
}

__device__ __forceinline__ uint32_t to_tf32(float f) {
    uint32_t r;
    asm("cvt.rna.tf32.f32 %0, %1;" : "=r"(r) : "f"(f));
    return r;
}

// Split fp32 bit-pattern x into tf32 hi + tf32 lo (residual)
__device__ __forceinline__ void split_tf32(uint32_t x, uint32_t& hi, uint32_t& lo) {
    float f = __uint_as_float(x);
    hi = to_tf32(f);
    lo = to_tf32(f - __uint_as_float(hi));
}

// fp32 -> tf32 hi (rna) + fp32 residual lo (residual consumed as truncated tf32
// by the MMA; second-order, fine)
__device__ __forceinline__ void fsplit(float f, float& h, float& l) {
    h = __uint_as_float(to_tf32(f));
    l = f - h;
}

__device__ __forceinline__ float fast_exp2(float x) {
    float r;
    asm("ex2.approx.ftz.f32 %0, %1;" : "=f"(r) : "f"(x));
    return r;
}

// ---------------------------------------------------------------------------
// Weight transpose: src [KDIM rows][cols] -> dst [cols][KDIM]
// ---------------------------------------------------------------------------
template <int WHICH>
__global__ __launch_bounds__(256) void transpose_kernel(const float* __restrict__ src, int cols)
{
    __shared__ float tile[32][33];
    float* dst = WHICH ? g_WtP : g_Wt;
    const int c0 = blockIdx.x * 32;
    const int r0 = blockIdx.y * 32;
    const int tx = threadIdx.x, ty = threadIdx.y;   // (32, 8)
#pragma unroll
    for (int j = 0; j < 32; j += 8)
        tile[ty + j][tx] = src[(size_t)(r0 + ty + j) * cols + c0 + tx];
    __syncthreads();
#pragma unroll
    for (int j = 0; j < 32; j += 8)
        dst[(size_t)(c0 + ty + j) * KDIM + r0 + tx] = tile[tx][ty + j];
}

// ---------------------------------------------------------------------------
// 3xTF32 mma.sync GEMM (unchanged from R4, passing)
// ---------------------------------------------------------------------------
#define GBM 128
#define GBN 128
#define GBK 32
#define NST 4
#define KTILES   (KDIM / GBK)           // 32
#define STAGE_B  (GBM * GBK * 4)        // 16384 bytes per matrix per stage
#define GSMEM    (2 * NST * STAGE_B)    // 131072

__device__ __forceinline__ void load_tile(uint32_t sA, uint32_t sB,
                                          const float* Ag, const float* Bg,
                                          int k0, int tid)
{
#pragma unroll
    for (int l = 0; l < 4; l++) {
        int idx = tid + l * 256;          // 0..1023
        int row = idx >> 3;               // 0..127
        int q   = idx & 7;                // 16B chunk along k
        uint32_t off = row * 128 + q * 16;
        uint32_t sw  = off ^ ((off >> 3) & 0x70);
        cp_async16(sA + sw, Ag + (size_t)row * KDIM + k0 + q * 4);
        cp_async16(sB + sw, Bg + (size_t)row * KDIM + k0 + q * 4);
    }
}

template <int N, int MODE>
__global__ __launch_bounds__(256) void tc_gemm(const float* __restrict__ Xin,
                                               const float* __restrict__ bias,
                                               float* __restrict__ out)
{
    extern __shared__ char smem[];
    const uint32_t sbase = smem_u32(smem);
    const int tid  = threadIdx.x;
    const int warp = tid >> 5;
    const int lane = tid & 31;
    const int wm = warp >> 1;             // 0..3
    const int wn = warp & 1;              // 0..1
    const int bm = blockIdx.y * GBM;
    const int bn = blockIdx.x * GBN;

    const float* A = ((MODE == 0) ? Xin : g_Y) + (size_t)bm * KDIM;
    const float* B = ((MODE == 0) ? g_Wt : g_WtP) + (size_t)bn * KDIM;

    const int arow = wm * 32 + (lane & 15);
    const uint32_t a_rowoff = (uint32_t)arow * 128;
    const int a_rx = arow & 7;
    const int acb = (lane >> 4) & 1;
    const int brow = wn * 64 + (lane & 7) + ((lane & 16) >> 1);
    const uint32_t b_rowoff = (uint32_t)brow * 128;
    const int b_rx = brow & 7;
    const int bcb = (lane >> 3) & 1;

    float acc[2][8][4];
#pragma unroll
    for (int mi = 0; mi < 2; mi++)
#pragma unroll
        for (int ni = 0; ni < 8; ni++)
#pragma unroll
            for (int r = 0; r < 4; r++) acc[mi][ni][r] = 0.0f;

#pragma unroll
    for (int t = 0; t < 3; t++) {
        load_tile(sbase + t * STAGE_B, sbase + (NST + t) * STAGE_B, A, B, t * GBK, tid);
        CP_COMMIT();
    }

    for (int t = 0; t < KTILES; t++) {
        if (t < KTILES - 2)
            asm volatile("cp.async.wait_group 2;" ::: "memory");
        else if (t == KTILES - 2)
            asm volatile("cp.async.wait_group 1;" ::: "memory");
        else
            asm volatile("cp.async.wait_group 0;" ::: "memory");
        __syncthreads();

        const uint32_t sA = sbase + (t & 3) * STAGE_B;
        const uint32_t sB = sbase + (NST + (t & 3)) * STAGE_B;

#pragma unroll
        for (int ks = 0; ks < 4; ks++) {
            uint32_t a[2][4], b[4][4];
#pragma unroll
            for (int mi = 0; mi < 2; mi++)
                ldsm_x4(a[mi], sA + a_rowoff + mi * 2048 +
                               (uint32_t)(((ks * 2 + acb) ^ a_rx) << 4));
#pragma unroll
            for (int pi = 0; pi < 4; pi++)
                ldsm_x4(b[pi], sB + b_rowoff + pi * 2048 +
                               (uint32_t)(((ks * 2 + bcb) ^ b_rx) << 4));

            uint32_t ah[2][4], al[2][4], bh[4][4], bl[4][4];
#pragma unroll
            for (int mi = 0; mi < 2; mi++)
#pragma unroll
                for (int j = 0; j < 4; j++)
                    split_tf32(a[mi][j], ah[mi][j], al[mi][j]);
#pragma unroll
            for (int pi = 0; pi < 4; pi++)
#pragma unroll
                for (int j = 0; j < 4; j++)
                    split_tf32(b[pi][j], bh[pi][j], bl[pi][j]);

#pragma unroll
            for (int mi = 0; mi < 2; mi++)
#pragma unroll
                for (int ni = 0; ni < 8; ni++) {
                    const int pi = ni >> 1;
                    const int j0 = (ni & 1) * 2;
                    mma_tf32(acc[mi][ni], al[mi], bh[pi][j0], bh[pi][j0 + 1]);
                    mma_tf32(acc[mi][ni], ah[mi], bl[pi][j0], bl[pi][j0 + 1]);
                    mma_tf32(acc[mi][ni], ah[mi], bh[pi][j0], bh[pi][j0 + 1]);
                }
        }

        if (t + 3 < KTILES) {
            const int tn = t + 3;
            load_tile(sbase + (tn & 3) * STAGE_B, sbase + (NST + (tn & 3)) * STAGE_B,
                      A, B, tn * GBK, tid);
            CP_COMMIT();
        }
    }

#pragma unroll
    for (int mi = 0; mi < 2; mi++) {
#pragma unroll
        for (int ni = 0; ni < 8; ni++) {
            const int col = bn + wn * 64 + ni * 8 + (lane & 3) * 2;
            float2 bv = *(const float2*)(bias + col);
#pragma unroll
            for (int half = 0; half < 2; half++) {
                const int row = bm + wm * 32 + mi * 16 + (lane >> 2) + half * 8;
                float2 v;
                v.x = acc[mi][ni][half * 2 + 0] + bv.x;
                v.y = acc[mi][ni][half * 2 + 1] + bv.y;
                if (MODE == 0) {
                    const int sec  = col >> 10;
                    const int cc   = col & 1023;
                    const int head = cc >> 6;
                    const int dpos = cc & 63;
                    const int b  = row >> 10;
                    const int tt = row & 1023;
                    float* basep = (sec == 0) ? g_Q : ((sec == 1) ? g_K : g_V);
                    *(float2*)(basep + (((size_t)(b * NH + head) * TSEQ + tt) * DH + dpos)) = v;
                } else {
                    *(float2*)(out + (size_t)row * N + col) = v;
                }
            }
        }
    }
}

// ---------------------------------------------------------------------------
// Tensor-core flash attention (3xTF32 everywhere, online softmax, causal).
// Grid: (T/128, B*H). Block 256 = 8 warps; warp w owns q-rows w*16..w*16+15.
// Key tiles of 64. Q/K/V pre-split hi/lo in smem; P split hi/lo at store.
// All padded smem panels: row stride 68 floats (272 B) -> conflict-free
// ldmatrix (banks advance by 4 per row).
// ---------------------------------------------------------------------------
#define ABQ   128
#define ABK   64
#define ASTB  272                 // row stride bytes (68 floats)
#define SQHI  0                   // 128 x 272 = 34816
#define SQLO  34816
#define SKHI  69632               // 64 x 272 = 17408
#define SKLO  87040
#define SVHI  104448              // V^T: 64 d-rows x 272
#define SVLO  121856
#define SPHI  139264              // 8 warps x 16 x 272 = 34816
#define SPLO  174080
#define ASMEM 208896

__global__ __launch_bounds__(256) void attn_kernel()
{
    extern __shared__ char smc[];
    const uint32_t sb = smem_u32(smc);
    float* smf = (float*)smc;

    const int qi = blockIdx.x;          // 0..7
    const int bh = blockIdx.y;
    const int bb = bh >> 4, hh = bh & 15;
    const float* Qb = g_Q + (size_t)bh * TSEQ * DH;
    const float* Kb = g_K + (size_t)bh * TSEQ * DH;
    const float* Vb = g_V + (size_t)bh * TSEQ * DH;

    const int tid  = threadIdx.x;
    const int warp = tid >> 5;
    const int lane = tid & 31;
    const int rA   = lane >> 2;         // local row (0..7); rB = rA+8
    const int qcol = (lane & 3) * 2;    // accumulator column base within octet

    // ldmatrix lane addressing (same recipe as validated GEMM)
    const int acb  = (lane >> 4) & 1;
    const int brow = (lane & 7) + ((lane & 16) >> 1);
    const int bcb  = (lane >> 3) & 1;

    // ---- Load + split Q tile [128 x 64] ----
    {
        const int row = tid >> 1;               // handled below via idx loop
        (void)row;
#pragma unroll
        for (int l = 0; l < 8; l++) {
            int idx = tid + l * 256;            // 0..2047
            int r  = idx >> 4;                  // 0..127
            int ch = idx & 15;                  // 16B chunk
            float4 v = *(const float4*)(Qb + (size_t)(qi * ABQ + r) * DH + ch * 4);
            float4 h4, l4;
            fsplit(v.x, h4.x, l4.x); fsplit(v.y, h4.y, l4.y);
            fsplit(v.z, h4.z, l4.z); fsplit(v.w, h4.w, l4.w);
            *(float4*)(smc + SQHI + r * ASTB + ch * 16) = h4;
            *(float4*)(smc + SQLO + r * ASTB + ch * 16) = l4;
        }
    }

    // Persistent state
    float o[8][4];
#pragma unroll
    for (int ni = 0; ni < 8; ni++)
#pragma unroll
        for (int j = 0; j < 4; j++) o[ni][j] = 0.0f;
    float mA = -1e30f, mB = -1e30f, lAcc = 0.0f, lBcc = 0.0f;

    const float CS = 0.18033688011112042f;   // 0.125 * log2(e)
    const int ntiles = 2 * qi + 2;

    // K prefetch: thread covers rows (tid>>4)+16l, chunk tid&15
    const int krow0 = tid >> 4;
    const int kch   = tid & 15;
    // V prefetch: key = tid>>2, dgroup = tid&3
    const int vkey = tid >> 2;
    const int vdg  = tid & 3;

    float4 kreg[4], vreg[4];
#pragma unroll
    for (int l = 0; l < 4; l++)
        kreg[l] = *(const float4*)(Kb + (size_t)(krow0 + 16 * l) * DH + kch * 4);
#pragma unroll
    for (int e = 0; e < 4; e++)
        vreg[e] = *(const float4*)(Vb + (size_t)vkey * DH + vdg * 16 + e * 4);

    for (int kt = 0; kt < ntiles; kt++) {
        __syncthreads();   // previous tile's compute fully consumed smem

        // Store + split K tile
#pragma unroll
        for (int l = 0; l < 4; l++) {
            int r = krow0 + 16 * l;
            float4 h4, l4;
            fsplit(kreg[l].x, h4.x, l4.x); fsplit(kreg[l].y, h4.y, l4.y);
            fsplit(kreg[l].z, h4.z, l4.z); fsplit(kreg[l].w, h4.w, l4.w);
            *(float4*)(smc + SKHI + r * ASTB + kch * 16) = h4;
            *(float4*)(smc + SKLO + r * ASTB + kch * 16) = l4;
        }
        // Store + split V^T tile (scalar transposed stores)
#pragma unroll
        for (int e = 0; e < 4; e++) {
            float vv[4] = {vreg[e].x, vreg[e].y, vreg[e].z, vreg[e].w};
#pragma unroll
            for (int i = 0; i < 4; i++) {
                int d = vdg * 16 + e * 4 + i;
                float h, lo;
                fsplit(vv[i], h, lo);
                smf[(SVHI >> 2) + d * 68 + vkey] = h;
                smf[(SVLO >> 2) + d * 68 + vkey] = lo;
            }
        }
        __syncthreads();

        // Prefetch next tile
        if (kt + 1 < ntiles) {
            const int nk = (kt + 1) * ABK;
#pragma unroll
            for (int l = 0; l < 4; l++)
                kreg[l] = *(const float4*)(Kb + (size_t)(nk + krow0 + 16 * l) * DH + kch * 4);
#pragma unroll
            for (int e = 0; e < 4; e++)
                vreg[e] = *(const float4*)(Vb + (size_t)(nk + vkey) * DH + vdg * 16 + e * 4);
        }

        // Does this warp have any visible keys in this tile?
        if (kt * ABK <= qi * ABQ + warp * 16 + 15) {
            // ---- S = Q K^T (3xtf32) ----
            float s[8][4];
#pragma unroll
            for (int ni = 0; ni < 8; ni++)
#pragma unroll
                for (int j = 0; j < 4; j++) s[ni][j] = 0.0f;

            const uint32_t qa = sb + (uint32_t)(warp * 16 + (lane & 15)) * ASTB + acb * 16;
            const uint32_t kb4 = sb + (uint32_t)brow * ASTB + bcb * 16;
#pragma unroll
            for (int ks = 0; ks < 8; ks++) {
                uint32_t ahv[4], alv[4], bhv[4][4], blv[4][4];
                ldsm_x4(ahv, qa + SQHI + ks * 32);
                ldsm_x4(alv, qa + SQLO + ks * 32);
#pragma unroll
                for (int pi = 0; pi < 4; pi++) {
                    ldsm_x4(bhv[pi], kb4 + SKHI + (uint32_t)pi * (16 * ASTB) + ks * 32);
                    ldsm_x4(blv[pi], kb4 + SKLO + (uint32_t)pi * (16 * ASTB) + ks * 32);
                }
#pragma unroll
                for (int ni = 0; ni < 8; ni++) {
                    const int pi = ni >> 1, j0 = (ni & 1) * 2;
                    mma_tf32(s[ni], alv, bhv[pi][j0], bhv[pi][j0 + 1]);
                    mma_tf32(s[ni], ahv, blv[pi][j0], blv[pi][j0 + 1]);
                    mma_tf32(s[ni], ahv, bhv[pi][j0], bhv[pi][j0 + 1]);
                }
            }

            // ---- scale + causal mask -> z ----
            const bool needmask = (kt * ABK + ABK - 1 > qi * ABQ + warp * 16);
            const int rowgA = qi * ABQ + warp * 16 + rA;
            const int rowgB = rowgA + 8;
            const int cb = kt * ABK + qcol;
#pragma unroll
            for (int ni = 0; ni < 8; ni++) {
                float z0 = s[ni][0] * CS, z1 = s[ni][1] * CS;
                float z2 = s[ni][2] * CS, z3 = s[ni][3] * CS;
                if (needmask) {
                    int c0 = cb + ni * 8, c1 = c0 + 1;
                    if (c0 > rowgA) z0 = -1e30f;
                    if (c1 > rowgA) z1 = -1e30f;
                    if (c0 > rowgB) z2 = -1e30f;
                    if (c1 > rowgB) z3 = -1e30f;
                }
                s[ni][0] = z0; s[ni][1] = z1; s[ni][2] = z2; s[ni][3] = z3;
            }

            // ---- online softmax (quad reductions) ----
            float mtA = -1e30f, mtB = -1e30f;
#pragma unroll
            for (int ni = 0; ni < 8; ni++) {
                mtA = fmaxf(mtA, fmaxf(s[ni][0], s[ni][1]));
                mtB = fmaxf(mtB, fmaxf(s[ni][2], s[ni][3]));
            }
            mtA = fmaxf(mtA, __shfl_xor_sync(0xffffffffu, mtA, 1));
            mtA = fmaxf(mtA, __shfl_xor_sync(0xffffffffu, mtA, 2));
            mtB = fmaxf(mtB, __shfl_xor_sync(0xffffffffu, mtB, 1));
            mtB = fmaxf(mtB, __shfl_xor_sync(0xffffffffu, mtB, 2));

            const float mnA = fmaxf(mA, mtA);
            const float mnB = fmaxf(mB, mtB);
            const float aAl = fast_exp2(mA - mnA);
            const float aBl = fast_exp2(mB - mnB);
            mA = mnA; mB = mnB;

            float psA = 0.0f, psB = 0.0f;
#pragma unroll
            for (int ni = 0; ni < 8; ni++) {
                float p0 = fast_exp2(s[ni][0] - mnA);
                float p1 = fast_exp2(s[ni][1] - mnA);
                float p2 = fast_exp2(s[ni][2] - mnB);
                float p3 = fast_exp2(s[ni][3] - mnB);
                psA += p0 + p1; psB += p2 + p3;
                s[ni][0] = p0; s[ni][1] = p1; s[ni][2] = p2; s[ni][3] = p3;
            }
            psA += __shfl_xor_sync(0xffffffffu, psA, 1);
            psA += __shfl_xor_sync(0xffffffffu, psA, 2);
            psB += __shfl_xor_sync(0xffffffffu, psB, 1);
            psB += __shfl_xor_sync(0xffffffffu, psB, 2);
            lAcc = lAcc * aAl + psA;
            lBcc = lBcc * aBl + psB;

#pragma unroll
            for (int ni = 0; ni < 8; ni++) {
                o[ni][0] *= aAl; o[ni][1] *= aAl;
                o[ni][2] *= aBl; o[ni][3] *= aBl;
            }

            // ---- store P hi/lo to warp-private smem ----
            const int pbaseH = (SPHI >> 2) + warp * (16 * 68);
            const int pbaseL = (SPLO >> 2) + warp * (16 * 68);
#pragma unroll
            for (int ni = 0; ni < 8; ni++) {
                int col = ni * 8 + qcol;
                float2 h0, l0, h1, l1;
                fsplit(s[ni][0], h0.x, l0.x); fsplit(s[ni][1], h0.y, l0.y);
                fsplit(s[ni][2], h1.x, l1.x); fsplit(s[ni][3], h1.y, l1.y);
                *(float2*)(smf + pbaseH + rA * 68 + col)      = h0;
                *(float2*)(smf + pbaseL + rA * 68 + col)      = l0;
                *(float2*)(smf + pbaseH + (rA + 8) * 68 + col) = h1;
                *(float2*)(smf + pbaseL + (rA + 8) * 68 + col) = l1;
            }
            __syncwarp();

            // ---- O += P V (3xtf32) ----
            const uint32_t pa = sb + (uint32_t)warp * (16 * ASTB)
                              + (uint32_t)(lane & 15) * ASTB + acb * 16;
            const uint32_t vb4 = sb + (uint32_t)brow * ASTB + bcb * 16;
#pragma unroll
            for (int ks = 0; ks < 8; ks++) {
                uint32_t phv[4], plv[4], vhv[4][4], vlv[4][4];
                ldsm_x4(phv, pa + SPHI + ks * 32);
                ldsm_x4(plv, pa + SPLO + ks * 32);
#pragma unroll
                for (int pi = 0; pi < 4; pi++) {
                    ldsm_x4(vhv[pi], vb4 + SVHI + (uint32_t)pi * (16 * ASTB) + ks * 32);
                    ldsm_x4(vlv[pi], vb4 + SVLO + (uint32_t)pi * (16 * ASTB) + ks * 32);
                }
#pragma unroll
                for (int ni = 0; ni < 8; ni++) {
                    const int pi = ni >> 1, j0 = (ni & 1) * 2;
                    mma_tf32(o[ni], plv, vhv[pi][j0], vhv[pi][j0 + 1]);
                    mma_tf32(o[ni], phv, vlv[pi][j0], vlv[pi][j0 + 1]);
                    mma_tf32(o[ni], phv, vhv[pi][j0], vhv[pi][j0 + 1]);
                }
            }
        }
    }

    // ---- epilogue: normalize + write to g_Y [b][t][h*64+d] ----
    const float invA = 1.0f / lAcc;
    const float invB = 1.0f / lBcc;
    const int tA = qi * ABQ + warp * 16 + rA;
    const int tB = tA + 8;
    const size_t baseA = ((size_t)bb * TSEQ + tA) * CDIM + hh * DH;
    const size_t baseB = ((size_t)bb * TSEQ + tB) * CDIM + hh * DH;
#pragma unroll
    for (int ni = 0; ni < 8; ni++) {
        int col = ni * 8 + qcol;
        float2 vA = make_float2(o[ni][0] * invA, o[ni][1] * invA);
        float2 vB = make_float2(o[ni][2] * invB, o[ni][3] * invB);
        *(float2*)(g_Y + baseA + col) = vA;
        *(float2*)(g_Y + baseB + col) = vB;
    }
}

// ---------------------------------------------------------------------------
// Launch
// ---------------------------------------------------------------------------
extern "C" void kernel_launch(void* const* d_in, const int* in_sizes, int n_in,
                              void* d_out, int out_size)
{
    const float* x      = (const float*)d_in[0];
    const float* w_attn = (const float*)d_in[1];
    const float* b_attn = (const float*)d_in[2];
    const float* w_proj = (const float*)d_in[3];
    const float* b_proj = (const float*)d_in[4];
    float* out = (float*)d_out;

    // 0) Transpose weights to [n][k]
    {
        dim3 blk(32, 8);
        transpose_kernel<0><<<dim3(3 * CDIM / 32, KDIM / 32), blk>>>(w_attn, 3 * CDIM);
        transpose_kernel<1><<<dim3(CDIM / 32, KDIM / 32), blk>>>(w_proj, CDIM);
    }

    // 1) QKV GEMM (3xtf32 mma.sync) + scatter to [b,h,t,d]
    {
        cudaFuncSetAttribute(tc_gemm<3 * CDIM, 0>,
                             cudaFuncAttributeMaxDynamicSharedMemorySize, GSMEM);
        dim3 grid(3 * CDIM / GBN, MROWS / GBM);   // (24, 32)
        tc_gemm<3 * CDIM, 0><<<grid, 256, GSMEM>>>(x, b_attn, nullptr);
    }

    // 2) Tensor-core flash attention
    {
        cudaFuncSetAttribute(attn_kernel,
                             cudaFuncAttributeMaxDynamicSharedMemorySize, ASMEM);
        dim3 grid(TSEQ / ABQ, NB * NH);           // (8, 64)
        attn_kernel<<<grid, 256, ASMEM>>>();
    }

    // 3) Output projection (3xtf32 mma.sync)
    {
        cudaFuncSetAttribute(tc_gemm<CDIM, 1>,
                             cudaFuncAttributeMaxDynamicSharedMemorySize, GSMEM);
        dim3 grid(CDIM / GBN, MROWS / GBM);       // (8, 32)
        tc_gemm<CDIM, 1><<<grid, 256, GSMEM>>>(nullptr, b_proj, out);
    }
}

// round 6
// speedup vs baseline: 2.4955x; 1.6080x over previous
#include <cuda_runtime.h>
#include <cuda_bf16.h>
#include <math.h>
#include <stdint.h>

// Problem constants
#define NB    4
#define TSEQ  1024
#define CDIM  1024
#define NH    16
#define DH    64
#define MROWS (NB * TSEQ)      // 4096
#define KDIM  1024

// Scratch (device globals -- no allocation allowed)
__device__ float g_Q[(size_t)NB * NH * TSEQ * DH];
__device__ float g_K[(size_t)NB * NH * TSEQ * DH];
__device__ float g_V[(size_t)NB * NH * TSEQ * DH];
__device__ float g_Y[(size_t)MROWS * CDIM];
// Pre-split bf16 operands
__device__ __nv_bfloat16 g_Xhi[(size_t)MROWS * KDIM];
__device__ __nv_bfloat16 g_Xlo[(size_t)MROWS * KDIM];
__device__ __nv_bfloat16 g_Yhi[(size_t)MROWS * KDIM];
__device__ __nv_bfloat16 g_Ylo[(size_t)MROWS * KDIM];
__device__ __nv_bfloat16 g_WAhi[(size_t)3 * CDIM * KDIM];   // w_attn^T [n][k]
__device__ __nv_bfloat16 g_WAlo[(size_t)3 * CDIM * KDIM];
__device__ __nv_bfloat16 g_WPhi[(size_t)CDIM * KDIM];       // w_proj^T [n][k]
__device__ __nv_bfloat16 g_WPlo[(size_t)CDIM * KDIM];

// ---------------------------------------------------------------------------
// Helpers
// ---------------------------------------------------------------------------
__device__ __forceinline__ uint32_t smem_u32(const void* p) {
    return (uint32_t)__cvta_generic_to_shared(p);
}

__device__ __forceinline__ void cp_async16(uint32_t saddr, const void* gptr) {
    asm volatile("cp.async.cg.shared.global [%0], [%1], 16;" :: "r"(saddr), "l"(gptr));
}
#define CP_COMMIT() asm volatile("cp.async.commit_group;" ::: "memory")

__device__ __forceinline__ void ldsm_x4(uint32_t* r, uint32_t addr) {
    asm volatile("ldmatrix.sync.aligned.m8n8.x4.shared.b16 {%0,%1,%2,%3}, [%4];"
                 : "=r"(r[0]), "=r"(r[1]), "=r"(r[2]), "=r"(r[3]) : "r"(addr));
}

__device__ __forceinline__ void mma_tf32(float* c, const uint32_t* a,
                                         uint32_t b0, uint32_t b1) {
    asm volatile(
        "mma.sync.aligned.m16n8k8.row.col.f32.tf32.tf32.f32 "
        "{%0,%1,%2,%3}, {%4,%5,%6,%7}, {%8,%9}, {%0,%1,%2,%3};"
        : "+f"(c[0]), "+f"(c[1]), "+f"(c[2]), "+f"(c[3])
        : "r"(a[0]), "r"(a[1]), "r"(a[2]), "r"(a[3]), "r"(b0), "r"(b1));
}

__device__ __forceinline__ void mma_bf16(float* c, const uint32_t* a,
                                         uint32_t b0, uint32_t b1) {
    asm volatile(
        "mma.sync.aligned.m16n8k16.row.col.f32.bf16.bf16.f32 "
        "{%0,%1,%2,%3}, {%4,%5,%6,%7}, {%8,%9}, {%0,%1,%2,%3};"
        : "+f"(c[0]), "+f"(c[1]), "+f"(c[2]), "+f"(c[3])
        : "r"(a[0]), "r"(a[1]), "r"(a[2]), "r"(a[3]), "r"(b0), "r"(b1));
}

__device__ __forceinline__ uint32_t to_tf32(float f) {
    uint32_t r;
    asm("cvt.rna.tf32.f32 %0, %1;" : "=r"(r) : "f"(f));
    return r;
}

// fp32 -> tf32 hi + fp32 residual (attention kernel)
__device__ __forceinline__ void fsplit(float f, float& h, float& l) {
    h = __uint_as_float(to_tf32(f));
    l = f - h;
}

// fp32 -> bf16 hi + bf16 lo (GEMM pre-split)
__device__ __forceinline__ void bsplit(float f, __nv_bfloat16& h, __nv_bfloat16& l) {
    h = __float2bfloat16_rn(f);
    l = __float2bfloat16_rn(f - __bfloat162float(h));
}

__device__ __forceinline__ float fast_exp2(float x) {
    float r;
    asm("ex2.approx.ftz.f32 %0, %1;" : "=f"(r) : "f"(x));
    return r;
}

// ---------------------------------------------------------------------------
// Weight transpose + bf16 split: src [KDIM][cols] -> hi/lo [cols][KDIM]
// ---------------------------------------------------------------------------
template <int WHICH>
__global__ __launch_bounds__(256) void transpose_split_kernel(const float* __restrict__ src,
                                                              int cols)
{
    __shared__ float tile[32][33];
    __nv_bfloat16* dh = WHICH ? g_WPhi : g_WAhi;
    __nv_bfloat16* dl = WHICH ? g_WPlo : g_WAlo;
    const int c0 = blockIdx.x * 32;
    const int r0 = blockIdx.y * 32;
    const int tx = threadIdx.x, ty = threadIdx.y;   // (32, 8)
#pragma unroll
    for (int j = 0; j < 32; j += 8)
        tile[ty + j][tx] = src[(size_t)(r0 + ty + j) * cols + c0 + tx];
    __syncthreads();
#pragma unroll
    for (int j = 0; j < 32; j += 8) {
        float f = tile[tx][ty + j];
        __nv_bfloat16 h, l;
        bsplit(f, h, l);
        size_t o = (size_t)(c0 + ty + j) * KDIM + r0 + tx;
        dh[o] = h;
        dl[o] = l;
    }
}

// ---------------------------------------------------------------------------
// Activation bf16 split: WHICH 0: x -> g_Xhi/lo; WHICH 1: g_Y -> g_Yhi/lo
// ---------------------------------------------------------------------------
template <int WHICH>
__global__ __launch_bounds__(256) void split_kernel(const float* __restrict__ xin)
{
    const float* s = WHICH ? g_Y : xin;
    __nv_bfloat16* dh = WHICH ? g_Yhi : g_Xhi;
    __nv_bfloat16* dl = WHICH ? g_Ylo : g_Xlo;
    size_t i = ((size_t)blockIdx.x * 256 + threadIdx.x) * 4;
    float4 v = *(const float4*)(s + i);
    __nv_bfloat16 h0, l0, h1, l1, h2, l2, h3, l3;
    bsplit(v.x, h0, l0); bsplit(v.y, h1, l1);
    bsplit(v.z, h2, l2); bsplit(v.w, h3, l3);
    __nv_bfloat162* ph = (__nv_bfloat162*)(dh + i);
    __nv_bfloat162* pl = (__nv_bfloat162*)(dl + i);
    __nv_bfloat162 a; a.x = h0; a.y = h1;
    __nv_bfloat162 b; b.x = h2; b.y = h3;
    ph[0] = a; ph[1] = b;
    a.x = l0; a.y = l1; b.x = l2; b.y = l3;
    pl[0] = a; pl[1] = b;
}

// ---------------------------------------------------------------------------
// 3xBF16 mma.sync GEMM: out[m][n] = sum_k A[m][k]*B[n][k] + bias[n]
// Pre-split bf16 operands. BM=BN=128, BK=64, 3-stage cp.async, 8 warps
// (4m x 2n), warp tile 32x64. MODE0 -> scatter g_Q/g_K/g_V; MODE1 -> out.
// ---------------------------------------------------------------------------
#define GBM 128
#define GBN 128
#define GBK 64
#define KTILES  (KDIM / GBK)            // 16
#define PANEL   16384                    // 128 rows x 128 B
#define STAGE   (4 * PANEL)              // AH, AL, BH, BL
#define GSMEM   (3 * STAGE)              // 196608
#define OAH 0
#define OAL 16384
#define OBH 32768
#define OBL 49152

__device__ __forceinline__ void load_tile_b(uint32_t sg,
        const __nv_bfloat16* Ah, const __nv_bfloat16* Al,
        const __nv_bfloat16* Bh, const __nv_bfloat16* Bl,
        int k0, int tid)
{
#pragma unroll
    for (int l = 0; l < 4; l++) {
        int idx = tid + l * 256;          // 0..1023
        int row = idx >> 3;               // 0..127
        int q   = idx & 7;                // 16B chunk along k (8 bf16)
        uint32_t off = row * 128 + q * 16;
        uint32_t sw  = off ^ ((off >> 3) & 0x70);
        const size_t g = (size_t)row * KDIM + k0 + q * 8;
        cp_async16(sg + OAH + sw, Ah + g);
        cp_async16(sg + OAL + sw, Al + g);
        cp_async16(sg + OBH + sw, Bh + g);
        cp_async16(sg + OBL + sw, Bl + g);
    }
}

template <int N, int MODE>
__global__ __launch_bounds__(256) void tc_gemm(const float* __restrict__ bias,
                                               float* __restrict__ out)
{
    extern __shared__ char smem[];
    const uint32_t sbase = smem_u32(smem);
    const int tid  = threadIdx.x;
    const int warp = tid >> 5;
    const int lane = tid & 31;
    const int wm = warp >> 1;             // 0..3
    const int wn = warp & 1;              // 0..1
    const int bm = blockIdx.y * GBM;
    const int bn = blockIdx.x * GBN;

    const __nv_bfloat16* Ah = ((MODE == 0) ? g_Xhi : g_Yhi) + (size_t)bm * KDIM;
    const __nv_bfloat16* Al = ((MODE == 0) ? g_Xlo : g_Ylo) + (size_t)bm * KDIM;
    const __nv_bfloat16* Bh = ((MODE == 0) ? g_WAhi : g_WPhi) + (size_t)bn * KDIM;
    const __nv_bfloat16* Bl = ((MODE == 0) ? g_WAlo : g_WPlo) + (size_t)bn * KDIM;

    // ldmatrix lane addressing (identical to validated tf32 recipe)
    const int arow = wm * 32 + (lane & 15);
    const uint32_t a_rowoff = (uint32_t)arow * 128;
    const int a_rx = arow & 7;
    const int acb = (lane >> 4) & 1;
    const int brow = wn * 64 + (lane & 7) + ((lane & 16) >> 1);
    const uint32_t b_rowoff = (uint32_t)brow * 128;
    const int b_rx = brow & 7;
    const int bcb = (lane >> 3) & 1;

    float acc[2][8][4];
#pragma unroll
    for (int mi = 0; mi < 2; mi++)
#pragma unroll
        for (int ni = 0; ni < 8; ni++)
#pragma unroll
            for (int r = 0; r < 4; r++) acc[mi][ni][r] = 0.0f;

    // Prologue: prefetch stages 0,1
#pragma unroll
    for (int t = 0; t < 2; t++) {
        load_tile_b(sbase + t * STAGE, Ah, Al, Bh, Bl, t * GBK, tid);
        CP_COMMIT();
    }

    for (int t = 0; t < KTILES; t++) {
        if (t < KTILES - 2)
            asm volatile("cp.async.wait_group 1;" ::: "memory");
        else
            asm volatile("cp.async.wait_group 0;" ::: "memory");
        __syncthreads();

        const uint32_t sg = sbase + (uint32_t)(t % 3) * STAGE;

#pragma unroll
        for (int ks = 0; ks < 4; ks++) {    // k16 steps over BK=64
            uint32_t ah[2][4], al[2][4], bh[4][4], bl[4][4];
#pragma unroll
            for (int mi = 0; mi < 2; mi++) {
                uint32_t ao = a_rowoff + mi * 2048 +
                              (uint32_t)(((ks * 2 + acb) ^ a_rx) << 4);
                ldsm_x4(ah[mi], sg + OAH + ao);
                ldsm_x4(al[mi], sg + OAL + ao);
            }
#pragma unroll
            for (int pi = 0; pi < 4; pi++) {
                uint32_t bo = b_rowoff + pi * 2048 +
                              (uint32_t)(((ks * 2 + bcb) ^ b_rx) << 4);
                ldsm_x4(bh[pi], sg + OBH + bo);
                ldsm_x4(bl[pi], sg + OBL + bo);
            }
#pragma unroll
            for (int mi = 0; mi < 2; mi++)
#pragma unroll
                for (int ni = 0; ni < 8; ni++) {
                    const int pi = ni >> 1;
                    const int j0 = (ni & 1) * 2;
                    mma_bf16(acc[mi][ni], al[mi], bh[pi][j0], bh[pi][j0 + 1]);
                    mma_bf16(acc[mi][ni], ah[mi], bl[pi][j0], bl[pi][j0 + 1]);
                    mma_bf16(acc[mi][ni], ah[mi], bh[pi][j0], bh[pi][j0 + 1]);
                }
        }

        if (t + 2 < KTILES) {
            load_tile_b(sbase + (uint32_t)((t + 2) % 3) * STAGE,
                        Ah, Al, Bh, Bl, (t + 2) * GBK, tid);
            CP_COMMIT();
        }
    }

    // Epilogue
#pragma unroll
    for (int mi = 0; mi < 2; mi++) {
#pragma unroll
        for (int ni = 0; ni < 8; ni++) {
            const int col = bn + wn * 64 + ni * 8 + (lane & 3) * 2;
            float2 bv = *(const float2*)(bias + col);
#pragma unroll
            for (int half = 0; half < 2; half++) {
                const int row = bm + wm * 32 + mi * 16 + (lane >> 2) + half * 8;
                float2 v;
                v.x = acc[mi][ni][half * 2 + 0] + bv.x;
                v.y = acc[mi][ni][half * 2 + 1] + bv.y;
                if (MODE == 0) {
                    const int sec  = col >> 10;
                    const int cc   = col & 1023;
                    const int head = cc >> 6;
                    const int dpos = cc & 63;
                    const int b  = row >> 10;
                    const int tt = row & 1023;
                    float* basep = (sec == 0) ? g_Q : ((sec == 1) ? g_K : g_V);
                    *(float2*)(basep + (((size_t)(b * NH + head) * TSEQ + tt) * DH + dpos)) = v;
                } else {
                    *(float2*)(out + (size_t)row * N + col) = v;
                }
            }
        }
    }
}

// ---------------------------------------------------------------------------
// Tensor-core flash attention (3xTF32, online softmax, causal) -- unchanged
// ---------------------------------------------------------------------------
#define ABQ   128
#define ABK   64
#define ASTB  272
#define SQHI  0
#define SQLO  34816
#define SKHI  69632
#define SKLO  87040
#define SVHI  104448
#define SVLO  121856
#define SPHI  139264
#define SPLO  174080
#define ASMEM 208896

__global__ __launch_bounds__(256) void attn_kernel()
{
    extern __shared__ char smc[];
    const uint32_t sb = smem_u32(smc);
    float* smf = (float*)smc;

    const int qi = blockIdx.x;
    const int bh = blockIdx.y;
    const int bb = bh >> 4, hh = bh & 15;
    const float* Qb = g_Q + (size_t)bh * TSEQ * DH;
    const float* Kb = g_K + (size_t)bh * TSEQ * DH;
    const float* Vb = g_V + (size_t)bh * TSEQ * DH;

    const int tid  = threadIdx.x;
    const int warp = tid >> 5;
    const int lane = tid & 31;
    const int rA   = lane >> 2;
    const int qcol = (lane & 3) * 2;

    const int acb  = (lane >> 4) & 1;
    const int brow = (lane & 7) + ((lane & 16) >> 1);
    const int bcb  = (lane >> 3) & 1;

#pragma unroll
    for (int l = 0; l < 8; l++) {
        int idx = tid + l * 256;
        int r  = idx >> 4;
        int ch = idx & 15;
        float4 v = *(const float4*)(Qb + (size_t)(qi * ABQ + r) * DH + ch * 4);
        float4 h4, l4;
        fsplit(v.x, h4.x, l4.x); fsplit(v.y, h4.y, l4.y);
        fsplit(v.z, h4.z, l4.z); fsplit(v.w, h4.w, l4.w);
        *(float4*)(smc + SQHI + r * ASTB + ch * 16) = h4;
        *(float4*)(smc + SQLO + r * ASTB + ch * 16) = l4;
    }

    float o[8][4];
#pragma unroll
    for (int ni = 0; ni < 8; ni++)
#pragma unroll
        for (int j = 0; j < 4; j++) o[ni][j] = 0.0f;
    float mA = -1e30f, mB = -1e30f, lAcc = 0.0f, lBcc = 0.0f;

    const float CS = 0.18033688011112042f;
    const int ntiles = 2 * qi + 2;

    const int krow0 = tid >> 4;
    const int kch   = tid & 15;
    const int vkey = tid >> 2;
    const int vdg  = tid & 3;

    float4 kreg[4], vreg[4];
#pragma unroll
    for (int l = 0; l < 4; l++)
        kreg[l] = *(const float4*)(Kb + (size_t)(krow0 + 16 * l) * DH + kch * 4);
#pragma unroll
    for (int e = 0; e < 4; e++)
        vreg[e] = *(const float4*)(Vb + (size_t)vkey * DH + vdg * 16 + e * 4);

    for (int kt = 0; kt < ntiles; kt++) {
        __syncthreads();

#pragma unroll
        for (int l = 0; l < 4; l++) {
            int r = krow0 + 16 * l;
            float4 h4, l4;
            fsplit(kreg[l].x, h4.x, l4.x); fsplit(kreg[l].y, h4.y, l4.y);
            fsplit(kreg[l].z, h4.z, l4.z); fsplit(kreg[l].w, h4.w, l4.w);
            *(float4*)(smc + SKHI + r * ASTB + kch * 16) = h4;
            *(float4*)(smc + SKLO + r * ASTB + kch * 16) = l4;
        }
#pragma unroll
        for (int e = 0; e < 4; e++) {
            float vv[4] = {vreg[e].x, vreg[e].y, vreg[e].z, vreg[e].w};
#pragma unroll
            for (int i = 0; i < 4; i++) {
                int d = vdg * 16 + e * 4 + i;
                float h, lo;
                fsplit(vv[i], h, lo);
                smf[(SVHI >> 2) + d * 68 + vkey] = h;
                smf[(SVLO >> 2) + d * 68 + vkey] = lo;
            }
        }
        __syncthreads();

        if (kt + 1 < ntiles) {
            const int nk = (kt + 1) * ABK;
#pragma unroll
            for (int l = 0; l < 4; l++)
                kreg[l] = *(const float4*)(Kb + (size_t)(nk + krow0 + 16 * l) * DH + kch * 4);
#pragma unroll
            for (int e = 0; e < 4; e++)
                vreg[e] = *(const float4*)(Vb + (size_t)(nk + vkey) * DH + vdg * 16 + e * 4);
        }

        if (kt * ABK <= qi * ABQ + warp * 16 + 15) {
            float s[8][4];
#pragma unroll
            for (int ni = 0; ni < 8; ni++)
#pragma unroll
                for (int j = 0; j < 4; j++) s[ni][j] = 0.0f;

            const uint32_t qa = sb + (uint32_t)(warp * 16 + (lane & 15)) * ASTB + acb * 16;
            const uint32_t kb4 = sb + (uint32_t)brow * ASTB + bcb * 16;
#pragma unroll
            for (int ks = 0; ks < 8; ks++) {
                uint32_t ahv[4], alv[4], bhv[4][4], blv[4][4];
                ldsm_x4(ahv, qa + SQHI + ks * 32);
                ldsm_x4(alv, qa + SQLO + ks * 32);
#pragma unroll
                for (int pi = 0; pi < 4; pi++) {
                    ldsm_x4(bhv[pi], kb4 + SKHI + (uint32_t)pi * (16 * ASTB) + ks * 32);
                    ldsm_x4(blv[pi], kb4 + SKLO + (uint32_t)pi * (16 * ASTB) + ks * 32);
                }
#pragma unroll
                for (int ni = 0; ni < 8; ni++) {
                    const int pi = ni >> 1, j0 = (ni & 1) * 2;
                    mma_tf32(s[ni], alv, bhv[pi][j0], bhv[pi][j0 + 1]);
                    mma_tf32(s[ni], ahv, blv[pi][j0], blv[pi][j0 + 1]);
                    mma_tf32(s[ni], ahv, bhv[pi][j0], bhv[pi][j0 + 1]);
                }
            }

            const bool needmask = (kt * ABK + ABK - 1 > qi * ABQ + warp * 16);
            const int rowgA = qi * ABQ + warp * 16 + rA;
            const int rowgB = rowgA + 8;
            const int cb = kt * ABK + qcol;
#pragma unroll
            for (int ni = 0; ni < 8; ni++) {
                float z0 = s[ni][0] * CS, z1 = s[ni][1] * CS;
                float z2 = s[ni][2] * CS, z3 = s[ni][3] * CS;
                if (needmask) {
                    int c0 = cb + ni * 8, c1 = c0 + 1;
                    if (c0 > rowgA) z0 = -1e30f;
                    if (c1 > rowgA) z1 = -1e30f;
                    if (c0 > rowgB) z2 = -1e30f;
                    if (c1 > rowgB) z3 = -1e30f;
                }
                s[ni][0] = z0; s[ni][1] = z1; s[ni][2] = z2; s[ni][3] = z3;
            }

            float mtA = -1e30f, mtB = -1e30f;
#pragma unroll
            for (int ni = 0; ni < 8; ni++) {
                mtA = fmaxf(mtA, fmaxf(s[ni][0], s[ni][1]));
                mtB = fmaxf(mtB, fmaxf(s[ni][2], s[ni][3]));
            }
            mtA = fmaxf(mtA, __shfl_xor_sync(0xffffffffu, mtA, 1));
            mtA = fmaxf(mtA, __shfl_xor_sync(0xffffffffu, mtA, 2));
            mtB = fmaxf(mtB, __shfl_xor_sync(0xffffffffu, mtB, 1));
            mtB = fmaxf(mtB, __shfl_xor_sync(0xffffffffu, mtB, 2));

            const float mnA = fmaxf(mA, mtA);
            const float mnB = fmaxf(mB, mtB);
            const float aAl = fast_exp2(mA - mnA);
            const float aBl = fast_exp2(mB - mnB);
            mA = mnA; mB = mnB;

            float psA = 0.0f, psB = 0.0f;
#pragma unroll
            for (int ni = 0; ni < 8; ni++) {
                float p0 = fast_exp2(s[ni][0] - mnA);
                float p1 = fast_exp2(s[ni][1] - mnA);
                float p2 = fast_exp2(s[ni][2] - mnB);
                float p3 = fast_exp2(s[ni][3] - mnB);
                psA += p0 + p1; psB += p2 + p3;
                s[ni][0] = p0; s[ni][1] = p1; s[ni][2] = p2; s[ni][3] = p3;
            }
            psA += __shfl_xor_sync(0xffffffffu, psA, 1);
            psA += __shfl_xor_sync(0xffffffffu, psA, 2);
            psB += __shfl_xor_sync(0xffffffffu, psB, 1);
            psB += __shfl_xor_sync(0xffffffffu, psB, 2);
            lAcc = lAcc * aAl + psA;
            lBcc = lBcc * aBl + psB;

#pragma unroll
            for (int ni = 0; ni < 8; ni++) {
                o[ni][0] *= aAl; o[ni][1] *= aAl;
                o[ni][2] *= aBl; o[ni][3] *= aBl;
            }

            const int pbaseH = (SPHI >> 2) + warp * (16 * 68);
            const int pbaseL = (SPLO >> 2) + warp * (16 * 68);
#pragma unroll
            for (int ni = 0; ni < 8; ni++) {
                int col = ni * 8 + qcol;
                float2 h0, l0, h1, l1;
                fsplit(s[ni][0], h0.x, l0.x); fsplit(s[ni][1], h0.y, l0.y);
                fsplit(s[ni][2], h1.x, l1.x); fsplit(s[ni][3], h1.y, l1.y);
                *(float2*)(smf + pbaseH + rA * 68 + col)      = h0;
                *(float2*)(smf + pbaseL + rA * 68 + col)      = l0;
                *(float2*)(smf + pbaseH + (rA + 8) * 68 + col) = h1;
                *(float2*)(smf + pbaseL + (rA + 8) * 68 + col) = l1;
            }
            __syncwarp();

            const uint32_t pa = sb + (uint32_t)warp * (16 * ASTB)
                              + (uint32_t)(lane & 15) * ASTB + acb * 16;
            const uint32_t vb4 = sb + (uint32_t)brow * ASTB + bcb * 16;
#pragma unroll
            for (int ks = 0; ks < 8; ks++) {
                uint32_t phv[4], plv[4], vhv[4][4], vlv[4][4];
                ldsm_x4(phv, pa + SPHI + ks * 32);
                ldsm_x4(plv, pa + SPLO + ks * 32);
#pragma unroll
                for (int pi = 0; pi < 4; pi++) {
                    ldsm_x4(vhv[pi], vb4 + SVHI + (uint32_t)pi * (16 * ASTB) + ks * 32);
                    ldsm_x4(vlv[pi], vb4 + SVLO + (uint32_t)pi * (16 * ASTB) + ks * 32);
                }
#pragma unroll
                for (int ni = 0; ni < 8; ni++) {
                    const int pi = ni >> 1, j0 = (ni & 1) * 2;
                    mma_tf32(o[ni], plv, vhv[pi][j0], vhv[pi][j0 + 1]);
                    mma_tf32(o[ni], phv, vlv[pi][j0], vlv[pi][j0 + 1]);
                    mma_tf32(o[ni], phv, vhv[pi][j0], vhv[pi][j0 + 1]);
                }
            }
        }
    }

    const float invA = 1.0f / lAcc;
    const float invB = 1.0f / lBcc;
    const int tA = qi * ABQ + warp * 16 + rA;
    const int tB = tA + 8;
    const size_t baseA = ((size_t)bb * TSEQ + tA) * CDIM + hh * DH;
    const size_t baseB = ((size_t)bb * TSEQ + tB) * CDIM + hh * DH;
#pragma unroll
    for (int ni = 0; ni < 8; ni++) {
        int col = ni * 8 + qcol;
        float2 vA = make_float2(o[ni][0] * invA, o[ni][1] * invA);
        float2 vB = make_float2(o[ni][2] * invB, o[ni][3] * invB);
        *(float2*)(g_Y + baseA + col) = vA;
        *(float2*)(g_Y + baseB + col) = vB;
    }
}

// ---------------------------------------------------------------------------
// Launch
// ---------------------------------------------------------------------------
extern "C" void kernel_launch(void* const* d_in, const int* in_sizes, int n_in,
                              void* d_out, int out_size)
{
    const float* x      = (const float*)d_in[0];
    const float* w_attn = (const float*)d_in[1];
    const float* b_attn = (const float*)d_in[2];
    const float* w_proj = (const float*)d_in[3];
    const float* b_proj = (const float*)d_in[4];
    float* out = (float*)d_out;

    // 0) Transpose + split weights; split x
    {
        dim3 blk(32, 8);
        transpose_split_kernel<0><<<dim3(3 * CDIM / 32, KDIM / 32), blk>>>(w_attn, 3 * CDIM);
        transpose_split_kernel<1><<<dim3(CDIM / 32, KDIM / 32), blk>>>(w_proj, CDIM);
        split_kernel<0><<<(MROWS * KDIM) / (256 * 4), 256>>>(x);
    }

    // 1) QKV GEMM (3xbf16 mma.sync) + scatter to [b,h,t,d]
    {
        cudaFuncSetAttribute(tc_gemm<3 * CDIM, 0>,
                             cudaFuncAttributeMaxDynamicSharedMemorySize, GSMEM);
        dim3 grid(3 * CDIM / GBN, MROWS / GBM);   // (24, 32)
        tc_gemm<3 * CDIM, 0><<<grid, 256, GSMEM>>>(b_attn, nullptr);
    }

    // 2) Tensor-core flash attention
    {
        cudaFuncSetAttribute(attn_kernel,
                             cudaFuncAttributeMaxDynamicSharedMemorySize, ASMEM);
        dim3 grid(TSEQ / ABQ, NB * NH);           // (8, 64)
        attn_kernel<<<grid, 256, ASMEM>>>();
    }

    // 3) Split Y, then output projection (3xbf16 mma.sync)
    {
        split_kernel<1><<<(MROWS * KDIM) / (256 * 4), 256>>>(nullptr);
        cudaFuncSetAttribute(tc_gemm<CDIM, 1>,
                             cudaFuncAttributeMaxDynamicSharedMemorySize, GSMEM);
        dim3 grid(CDIM / GBN, MROWS / GBM);       // (8, 32)
        tc_gemm<CDIM, 1><<<grid, 256, GSMEM>>>(b_proj, out);
    }
}

// round 7
// speedup vs baseline: 3.0619x; 1.2270x over previous
#include <cuda_runtime.h>
#include <cuda_bf16.h>
#include <math.h>
#include <stdint.h>

// Problem constants
#define NB    4
#define TSEQ  1024
#define CDIM  1024
#define NH    16
#define DH    64
#define MROWS (NB * TSEQ)      // 4096
#define KDIM  1024

// Scratch (device globals -- no allocation allowed)
// Pre-split bf16 operands for GEMMs
__device__ __nv_bfloat16 g_Xhi[(size_t)MROWS * KDIM];
__device__ __nv_bfloat16 g_Xlo[(size_t)MROWS * KDIM];
__device__ __nv_bfloat16 g_Yhi[(size_t)MROWS * KDIM];
__device__ __nv_bfloat16 g_Ylo[(size_t)MROWS * KDIM];
__device__ __nv_bfloat16 g_WAhi[(size_t)3 * CDIM * KDIM];   // w_attn^T [n][k]
__device__ __nv_bfloat16 g_WAlo[(size_t)3 * CDIM * KDIM];
__device__ __nv_bfloat16 g_WPhi[(size_t)CDIM * KDIM];       // w_proj^T [n][k]
__device__ __nv_bfloat16 g_WPlo[(size_t)CDIM * KDIM];
// Pre-split attention operands: Q,K [bh][t][d]; V transposed [bh][d][t]
__device__ __nv_bfloat16 g_Qh[(size_t)NB * NH * TSEQ * DH];
__device__ __nv_bfloat16 g_Qlo[(size_t)NB * NH * TSEQ * DH];
__device__ __nv_bfloat16 g_Kh[(size_t)NB * NH * TSEQ * DH];
__device__ __nv_bfloat16 g_Klo[(size_t)NB * NH * TSEQ * DH];
__device__ __nv_bfloat16 g_Vth[(size_t)NB * NH * DH * TSEQ];
__device__ __nv_bfloat16 g_Vtl[(size_t)NB * NH * DH * TSEQ];

// ---------------------------------------------------------------------------
// Helpers
// ---------------------------------------------------------------------------
__device__ __forceinline__ uint32_t smem_u32(const void* p) {
    return (uint32_t)__cvta_generic_to_shared(p);
}

__device__ __forceinline__ void cp_async16(uint32_t saddr, const void* gptr) {
    asm volatile("cp.async.cg.shared.global [%0], [%1], 16;" :: "r"(saddr), "l"(gptr));
}
#define CP_COMMIT() asm volatile("cp.async.commit_group;" ::: "memory")

__device__ __forceinline__ void ldsm_x4(uint32_t* r, uint32_t addr) {
    asm volatile("ldmatrix.sync.aligned.m8n8.x4.shared.b16 {%0,%1,%2,%3}, [%4];"
                 : "=r"(r[0]), "=r"(r[1]), "=r"(r[2]), "=r"(r[3]) : "r"(addr));
}

__device__ __forceinline__ void mma_bf16(float* c, const uint32_t* a,
                                         uint32_t b0, uint32_t b1) {
    asm volatile(
        "mma.sync.aligned.m16n8k16.row.col.f32.bf16.bf16.f32 "
        "{%0,%1,%2,%3}, {%4,%5,%6,%7}, {%8,%9}, {%0,%1,%2,%3};"
        : "+f"(c[0]), "+f"(c[1]), "+f"(c[2]), "+f"(c[3])
        : "r"(a[0]), "r"(a[1]), "r"(a[2]), "r"(a[3]), "r"(b0), "r"(b1));
}

// fp32 -> bf16 hi + bf16 lo
__device__ __forceinline__ void bsplit(float f, __nv_bfloat16& h, __nv_bfloat16& l) {
    h = __float2bfloat16_rn(f);
    l = __float2bfloat16_rn(f - __bfloat162float(h));
}

__device__ __forceinline__ float fast_exp2(float x) {
    float r;
    asm("ex2.approx.ftz.f32 %0, %1;" : "=f"(r) : "f"(x));
    return r;
}

// ---------------------------------------------------------------------------
// Weight transpose + bf16 split: src [KDIM][cols] -> hi/lo [cols][KDIM]
// ---------------------------------------------------------------------------
template <int WHICH>
__global__ __launch_bounds__(256) void transpose_split_kernel(const float* __restrict__ src,
                                                              int cols)
{
    __shared__ float tile[32][33];
    __nv_bfloat16* dh = WHICH ? g_WPhi : g_WAhi;
    __nv_bfloat16* dl = WHICH ? g_WPlo : g_WAlo;
    const int c0 = blockIdx.x * 32;
    const int r0 = blockIdx.y * 32;
    const int tx = threadIdx.x, ty = threadIdx.y;   // (32, 8)
#pragma unroll
    for (int j = 0; j < 32; j += 8)
        tile[ty + j][tx] = src[(size_t)(r0 + ty + j) * cols + c0 + tx];
    __syncthreads();
#pragma unroll
    for (int j = 0; j < 32; j += 8) {
        float f = tile[tx][ty + j];
        __nv_bfloat16 h, l;
        bsplit(f, h, l);
        size_t o = (size_t)(c0 + ty + j) * KDIM + r0 + tx;
        dh[o] = h;
        dl[o] = l;
    }
}

// ---------------------------------------------------------------------------
// Activation bf16 split for x -> g_Xhi/lo
// ---------------------------------------------------------------------------
__global__ __launch_bounds__(256) void split_kernel(const float* __restrict__ xin)
{
    size_t i = ((size_t)blockIdx.x * 256 + threadIdx.x) * 4;
    float4 v = *(const float4*)(xin + i);
    __nv_bfloat16 h0, l0, h1, l1, h2, l2, h3, l3;
    bsplit(v.x, h0, l0); bsplit(v.y, h1, l1);
    bsplit(v.z, h2, l2); bsplit(v.w, h3, l3);
    __nv_bfloat162* ph = (__nv_bfloat162*)(g_Xhi + i);
    __nv_bfloat162* pl = (__nv_bfloat162*)(g_Xlo + i);
    __nv_bfloat162 a; a.x = h0; a.y = h1;
    __nv_bfloat162 b; b.x = h2; b.y = h3;
    ph[0] = a; ph[1] = b;
    a.x = l0; a.y = l1; b.x = l2; b.y = l3;
    pl[0] = a; pl[1] = b;
}

// ---------------------------------------------------------------------------
// 3xBF16 mma.sync GEMM.
// MODE0: QKV -> write pre-split bf16 Q/K ([bh][t][d]) and V^T ([bh][d][t])
// MODE1: proj -> out fp32 [m][n]
// ---------------------------------------------------------------------------
#define GBM 128
#define GBN 128
#define GBK 64
#define KTILES  (KDIM / GBK)            // 16
#define PANEL   16384                    // 128 rows x 128 B
#define STAGE   (4 * PANEL)              // AH, AL, BH, BL
#define GSMEM   (3 * STAGE)              // 196608
#define OAH 0
#define OAL 16384
#define OBH 32768
#define OBL 49152

__device__ __forceinline__ void load_tile_b(uint32_t sg,
        const __nv_bfloat16* Ah, const __nv_bfloat16* Al,
        const __nv_bfloat16* Bh, const __nv_bfloat16* Bl,
        int k0, int tid)
{
#pragma unroll
    for (int l = 0; l < 4; l++) {
        int idx = tid + l * 256;          // 0..1023
        int row = idx >> 3;               // 0..127
        int q   = idx & 7;                // 16B chunk along k (8 bf16)
        uint32_t off = row * 128 + q * 16;
        uint32_t sw  = off ^ ((off >> 3) & 0x70);
        const size_t g = (size_t)row * KDIM + k0 + q * 8;
        cp_async16(sg + OAH + sw, Ah + g);
        cp_async16(sg + OAL + sw, Al + g);
        cp_async16(sg + OBH + sw, Bh + g);
        cp_async16(sg + OBL + sw, Bl + g);
    }
}

template <int N, int MODE>
__global__ __launch_bounds__(256) void tc_gemm(const float* __restrict__ bias,
                                               float* __restrict__ out)
{
    extern __shared__ char smem[];
    const uint32_t sbase = smem_u32(smem);
    const int tid  = threadIdx.x;
    const int warp = tid >> 5;
    const int lane = tid & 31;
    const int wm = warp >> 1;             // 0..3
    const int wn = warp & 1;              // 0..1
    const int bm = blockIdx.y * GBM;
    const int bn = blockIdx.x * GBN;

    const __nv_bfloat16* Ah = ((MODE == 0) ? g_Xhi : g_Yhi) + (size_t)bm * KDIM;
    const __nv_bfloat16* Al = ((MODE == 0) ? g_Xlo : g_Ylo) + (size_t)bm * KDIM;
    const __nv_bfloat16* Bh = ((MODE == 0) ? g_WAhi : g_WPhi) + (size_t)bn * KDIM;
    const __nv_bfloat16* Bl = ((MODE == 0) ? g_WAlo : g_WPlo) + (size_t)bn * KDIM;

    const int arow = wm * 32 + (lane & 15);
    const uint32_t a_rowoff = (uint32_t)arow * 128;
    const int a_rx = arow & 7;
    const int acb = (lane >> 4) & 1;
    const int brow = wn * 64 + (lane & 7) + ((lane & 16) >> 1);
    const uint32_t b_rowoff = (uint32_t)brow * 128;
    const int b_rx = brow & 7;
    const int bcb = (lane >> 3) & 1;

    float acc[2][8][4];
#pragma unroll
    for (int mi = 0; mi < 2; mi++)
#pragma unroll
        for (int ni = 0; ni < 8; ni++)
#pragma unroll
            for (int r = 0; r < 4; r++) acc[mi][ni][r] = 0.0f;

#pragma unroll
    for (int t = 0; t < 2; t++) {
        load_tile_b(sbase + t * STAGE, Ah, Al, Bh, Bl, t * GBK, tid);
        CP_COMMIT();
    }

    for (int t = 0; t < KTILES; t++) {
        if (t < KTILES - 2)
            asm volatile("cp.async.wait_group 1;" ::: "memory");
        else
            asm volatile("cp.async.wait_group 0;" ::: "memory");
        __syncthreads();

        const uint32_t sg = sbase + (uint32_t)(t % 3) * STAGE;

#pragma unroll
        for (int ks = 0; ks < 4; ks++) {
            uint32_t ah[2][4], al[2][4], bh[4][4], bl[4][4];
#pragma unroll
            for (int mi = 0; mi < 2; mi++) {
                uint32_t ao = a_rowoff + mi * 2048 +
                              (uint32_t)(((ks * 2 + acb) ^ a_rx) << 4);
                ldsm_x4(ah[mi], sg + OAH + ao);
                ldsm_x4(al[mi], sg + OAL + ao);
            }
#pragma unroll
            for (int pi = 0; pi < 4; pi++) {
                uint32_t bo = b_rowoff + pi * 2048 +
                              (uint32_t)(((ks * 2 + bcb) ^ b_rx) << 4);
                ldsm_x4(bh[pi], sg + OBH + bo);
                ldsm_x4(bl[pi], sg + OBL + bo);
            }
#pragma unroll
            for (int mi = 0; mi < 2; mi++)
#pragma unroll
                for (int ni = 0; ni < 8; ni++) {
                    const int pi = ni >> 1;
                    const int j0 = (ni & 1) * 2;
                    mma_bf16(acc[mi][ni], al[mi], bh[pi][j0], bh[pi][j0 + 1]);
                    mma_bf16(acc[mi][ni], ah[mi], bl[pi][j0], bl[pi][j0 + 1]);
                    mma_bf16(acc[mi][ni], ah[mi], bh[pi][j0], bh[pi][j0 + 1]);
                }
        }

        if (t + 2 < KTILES) {
            load_tile_b(sbase + (uint32_t)((t + 2) % 3) * STAGE,
                        Ah, Al, Bh, Bl, (t + 2) * GBK, tid);
            CP_COMMIT();
        }
    }

    // Epilogue
#pragma unroll
    for (int mi = 0; mi < 2; mi++) {
#pragma unroll
        for (int ni = 0; ni < 8; ni++) {
            const int col = bn + wn * 64 + ni * 8 + (lane & 3) * 2;
            float2 bv = *(const float2*)(bias + col);
#pragma unroll
            for (int half = 0; half < 2; half++) {
                const int row = bm + wm * 32 + mi * 16 + (lane >> 2) + half * 8;
                float vx = acc[mi][ni][half * 2 + 0] + bv.x;
                float vy = acc[mi][ni][half * 2 + 1] + bv.y;
                if (MODE == 0) {
                    const int sec  = col >> 10;          // 0=q, 1=k, 2=v
                    const int cc   = col & 1023;
                    const int head = cc >> 6;
                    const int dpos = cc & 63;
                    const int b  = row >> 10;
                    const int tt = row & 1023;
                    const int bh2 = b * NH + head;
                    __nv_bfloat16 hx, lx, hy, ly;
                    bsplit(vx, hx, lx); bsplit(vy, hy, ly);
                    if (sec < 2) {
                        size_t o = ((size_t)bh2 * TSEQ + tt) * DH + dpos;
                        __nv_bfloat162 hv; hv.x = hx; hv.y = hy;
                        __nv_bfloat162 lv; lv.x = lx; lv.y = ly;
                        if (sec == 0) {
                            *(__nv_bfloat162*)(g_Qh + o) = hv;
                            *(__nv_bfloat162*)(g_Qlo + o) = lv;
                        } else {
                            *(__nv_bfloat162*)(g_Kh + o) = hv;
                            *(__nv_bfloat162*)(g_Klo + o) = lv;
                        }
                    } else {
                        // V transposed: [bh][d][t]
                        size_t o0 = ((size_t)bh2 * DH + dpos) * TSEQ + tt;
                        g_Vth[o0] = hx; g_Vtl[o0] = lx;
                        g_Vth[o0 + TSEQ] = hy; g_Vtl[o0 + TSEQ] = ly;
                    }
                } else {
                    float2 v2; v2.x = vx; v2.y = vy;
                    *(float2*)(out + (size_t)row * N + col) = v2;
                }
            }
        }
    }
}

// ---------------------------------------------------------------------------
// Tensor-core flash attention, 3xBF16 everywhere, pre-split operands.
// Grid: (T/128, B*H). Block 256 = 8 warps; warp w owns q-rows w*16..w*16+15.
// Key tiles of 64. All smem panels: 128 B rows, xor swizzle.
// Writes Y directly as bf16 hi/lo ([b][t][c]) for the proj GEMM.
// ---------------------------------------------------------------------------
#define ABQ   128
#define ABK   64
#define SQH 0
#define SQL 16384
#define SKH 32768
#define SKL 40960
#define SVH 49152
#define SVL 57344
#define SPH 65536
#define SPL 81920
#define ASMEM 98304

__global__ __launch_bounds__(256, 2) void attn_kernel()
{
    extern __shared__ char smc[];
    const uint32_t sb = smem_u32(smc);

    const int qi = blockIdx.x;
    const int bh = blockIdx.y;
    const int bb = bh >> 4, hh = bh & 15;
    const __nv_bfloat16* Qhp = g_Qh  + (size_t)bh * TSEQ * DH;
    const __nv_bfloat16* Qlp = g_Qlo + (size_t)bh * TSEQ * DH;
    const __nv_bfloat16* Khp = g_Kh  + (size_t)bh * TSEQ * DH;
    const __nv_bfloat16* Klp = g_Klo + (size_t)bh * TSEQ * DH;
    const __nv_bfloat16* Vhp = g_Vth + (size_t)bh * DH * TSEQ;
    const __nv_bfloat16* Vlp = g_Vtl + (size_t)bh * DH * TSEQ;

    const int tid  = threadIdx.x;
    const int warp = tid >> 5;
    const int lane = tid & 31;
    const int rA   = lane >> 2;
    const int qcol = (lane & 3) * 2;

    const int acb  = (lane >> 4) & 1;
    const int bcb  = (lane >> 3) & 1;
    const int brow = (lane & 7) + ((lane & 16) >> 1);

    // Q panels: 128 rows x 128 B, hi+lo (committed with first K/V group)
#pragma unroll
    for (int l = 0; l < 8; l++) {
        int idx = tid + l * 256;
        int panel = idx >> 10;
        int rem = idx & 1023;
        int r = rem >> 3, ch = rem & 7;
        uint32_t off = (uint32_t)r * 128 + ch * 16;
        uint32_t sw = off ^ ((off >> 3) & 0x70);
        const __nv_bfloat16* src = (panel ? Qlp : Qhp) + (size_t)(qi * ABQ + r) * DH + ch * 8;
        cp_async16(sb + (panel ? SQL : SQH) + sw, src);
    }

    float o[8][4];
#pragma unroll
    for (int ni = 0; ni < 8; ni++)
#pragma unroll
        for (int j = 0; j < 4; j++) o[ni][j] = 0.0f;
    float mA = -1e30f, mB = -1e30f, lAcc = 0.0f, lBcc = 0.0f;

    const float CS = 0.18033688011112042f;   // 0.125 * log2(e)
    const int ntiles = 2 * qi + 2;

    for (int kt = 0; kt < ntiles; kt++) {
        __syncthreads();   // previous tile consumed
        // K + V^T panels: 64 rows x 128 B each, hi+lo
#pragma unroll
        for (int l = 0; l < 4; l++) {
            int idx = tid + l * 256;
            int panel = idx >> 9;
            int rem = idx & 511;
            int r = rem >> 3, ch = rem & 7;
            uint32_t off = (uint32_t)r * 128 + ch * 16;
            uint32_t sw = off ^ ((off >> 3) & 0x70);
            cp_async16(sb + (panel ? SKL : SKH) + sw,
                       (panel ? Klp : Khp) + (size_t)(kt * ABK + r) * DH + ch * 8);
            cp_async16(sb + (panel ? SVL : SVH) + sw,
                       (panel ? Vlp : Vhp) + (size_t)r * TSEQ + kt * ABK + ch * 8);
        }
        CP_COMMIT();
        asm volatile("cp.async.wait_group 0;" ::: "memory");
        __syncthreads();

        if (kt * ABK <= qi * ABQ + warp * 16 + 15) {
            // ---- S = Q K^T (3xbf16) ----
            float s[8][4];
#pragma unroll
            for (int ni = 0; ni < 8; ni++)
#pragma unroll
                for (int j = 0; j < 4; j++) s[ni][j] = 0.0f;

            const int aQrow = warp * 16 + (lane & 15);
            const uint32_t a_ro = (uint32_t)aQrow * 128;
            const int a_rx = aQrow & 7;
#pragma unroll
            for (int ks = 0; ks < 4; ks++) {
                uint32_t ah[4], al[4], kh[4][4], kl[4][4];
                uint32_t ao = a_ro + (uint32_t)(((ks * 2 + acb) ^ a_rx) << 4);
                ldsm_x4(ah, sb + SQH + ao);
                ldsm_x4(al, sb + SQL + ao);
#pragma unroll
                for (int pi = 0; pi < 4; pi++) {
                    int br = pi * 16 + brow;
                    uint32_t bo = (uint32_t)br * 128 +
                                  (uint32_t)(((ks * 2 + bcb) ^ (br & 7)) << 4);
                    ldsm_x4(kh[pi], sb + SKH + bo);
                    ldsm_x4(kl[pi], sb + SKL + bo);
                }
#pragma unroll
                for (int ni = 0; ni < 8; ni++) {
                    const int pi = ni >> 1, j0 = (ni & 1) * 2;
                    mma_bf16(s[ni], al, kh[pi][j0], kh[pi][j0 + 1]);
                    mma_bf16(s[ni], ah, kl[pi][j0], kl[pi][j0 + 1]);
                    mma_bf16(s[ni], ah, kh[pi][j0], kh[pi][j0 + 1]);
                }
            }

            // ---- scale + causal mask ----
            const bool needmask = (kt * ABK + ABK - 1 > qi * ABQ + warp * 16);
            const int rowgA = qi * ABQ + warp * 16 + rA;
            const int rowgB = rowgA + 8;
            const int cb = kt * ABK + qcol;
#pragma unroll
            for (int ni = 0; ni < 8; ni++) {
                float z0 = s[ni][0] * CS, z1 = s[ni][1] * CS;
                float z2 = s[ni][2] * CS, z3 = s[ni][3] * CS;
                if (needmask) {
                    int c0 = cb + ni * 8, c1 = c0 + 1;
                    if (c0 > rowgA) z0 = -1e30f;
                    if (c1 > rowgA) z1 = -1e30f;
                    if (c0 > rowgB) z2 = -1e30f;
                    if (c1 > rowgB) z3 = -1e30f;
                }
                s[ni][0] = z0; s[ni][1] = z1; s[ni][2] = z2; s[ni][3] = z3;
            }

            // ---- online softmax ----
            float mtA = -1e30f, mtB = -1e30f;
#pragma unroll
            for (int ni = 0; ni < 8; ni++) {
                mtA = fmaxf(mtA, fmaxf(s[ni][0], s[ni][1]));
                mtB = fmaxf(mtB, fmaxf(s[ni][2], s[ni][3]));
            }
            mtA = fmaxf(mtA, __shfl_xor_sync(0xffffffffu, mtA, 1));
            mtA = fmaxf(mtA, __shfl_xor_sync(0xffffffffu, mtA, 2));
            mtB = fmaxf(mtB, __shfl_xor_sync(0xffffffffu, mtB, 1));
            mtB = fmaxf(mtB, __shfl_xor_sync(0xffffffffu, mtB, 2));

            const float mnA = fmaxf(mA, mtA);
            const float mnB = fmaxf(mB, mtB);
            const float aAl = fast_exp2(mA - mnA);
            const float aBl = fast_exp2(mB - mnB);
            mA = mnA; mB = mnB;

            float psA = 0.0f, psB = 0.0f;
#pragma unroll
            for (int ni = 0; ni < 8; ni++) {
                float p0 = fast_exp2(s[ni][0] - mnA);
                float p1 = fast_exp2(s[ni][1] - mnA);
                float p2 = fast_exp2(s[ni][2] - mnB);
                float p3 = fast_exp2(s[ni][3] - mnB);
                psA += p0 + p1; psB += p2 + p3;
                s[ni][0] = p0; s[ni][1] = p1; s[ni][2] = p2; s[ni][3] = p3;
            }
            psA += __shfl_xor_sync(0xffffffffu, psA, 1);
            psA += __shfl_xor_sync(0xffffffffu, psA, 2);
            psB += __shfl_xor_sync(0xffffffffu, psB, 1);
            psB += __shfl_xor_sync(0xffffffffu, psB, 2);
            lAcc = lAcc * aAl + psA;
            lBcc = lBcc * aBl + psB;

#pragma unroll
            for (int ni = 0; ni < 8; ni++) {
                o[ni][0] *= aAl; o[ni][1] *= aAl;
                o[ni][2] *= aBl; o[ni][3] *= aBl;
            }

            // ---- store P (bf16 hi/lo packed) to warp-private panel rows ----
#pragma unroll
            for (int ni = 0; ni < 8; ni++) {
                int col = ni * 8 + qcol;
                __nv_bfloat16 h0, l0, h1, l1, h2, l2, h3, l3;
                bsplit(s[ni][0], h0, l0); bsplit(s[ni][1], h1, l1);
                bsplit(s[ni][2], h2, l2); bsplit(s[ni][3], h3, l3);
                int r0 = warp * 16 + rA, r1 = r0 + 8;
                uint32_t off0 = (uint32_t)r0 * 128 + col * 2;
                uint32_t off1 = (uint32_t)r1 * 128 + col * 2;
                uint32_t sw0 = off0 ^ ((off0 >> 3) & 0x70);
                uint32_t sw1 = off1 ^ ((off1 >> 3) & 0x70);
                __nv_bfloat162 hv, lv;
                hv.x = h0; hv.y = h1; lv.x = l0; lv.y = l1;
                *(__nv_bfloat162*)(smc + SPH + sw0) = hv;
                *(__nv_bfloat162*)(smc + SPL + sw0) = lv;
                hv.x = h2; hv.y = h3; lv.x = l2; lv.y = l3;
                *(__nv_bfloat162*)(smc + SPH + sw1) = hv;
                *(__nv_bfloat162*)(smc + SPL + sw1) = lv;
            }
            __syncwarp();

            // ---- O += P V (3xbf16) ----
            const int aProw = warp * 16 + (lane & 15);
            const uint32_t p_ro = (uint32_t)aProw * 128;
            const int p_rx = aProw & 7;
#pragma unroll
            for (int ks = 0; ks < 4; ks++) {
                uint32_t ph[4], pl[4], vh[4][4], vl[4][4];
                uint32_t ao = p_ro + (uint32_t)(((ks * 2 + acb) ^ p_rx) << 4);
                ldsm_x4(ph, sb + SPH + ao);
                ldsm_x4(pl, sb + SPL + ao);
#pragma unroll
                for (int pi = 0; pi < 4; pi++) {
                    int br = pi * 16 + brow;
                    uint32_t bo = (uint32_t)br * 128 +
                                  (uint32_t)(((ks * 2 + bcb) ^ (br & 7)) << 4);
                    ldsm_x4(vh[pi], sb + SVH + bo);
                    ldsm_x4(vl[pi], sb + SVL + bo);
                }
#pragma unroll
                for (int ni = 0; ni < 8; ni++) {
                    const int pi = ni >> 1, j0 = (ni & 1) * 2;
                    mma_bf16(o[ni], pl, vh[pi][j0], vh[pi][j0 + 1]);
                    mma_bf16(o[ni], ph, vl[pi][j0], vl[pi][j0 + 1]);
                    mma_bf16(o[ni], ph, vh[pi][j0], vh[pi][j0 + 1]);
                }
            }
        }
    }

    // ---- epilogue: normalize, split to bf16, write g_Yhi/lo [b][t][c] ----
    const float invA = 1.0f / lAcc;
    const float invB = 1.0f / lBcc;
    const int tA = qi * ABQ + warp * 16 + rA;
    const int tB = tA + 8;
    const size_t baseA = ((size_t)bb * TSEQ + tA) * CDIM + hh * DH;
    const size_t baseB = ((size_t)bb * TSEQ + tB) * CDIM + hh * DH;
#pragma unroll
    for (int ni = 0; ni < 8; ni++) {
        int col = ni * 8 + qcol;
        float yA0 = o[ni][0] * invA, yA1 = o[ni][1] * invA;
        float yB0 = o[ni][2] * invB, yB1 = o[ni][3] * invB;
        __nv_bfloat16 h0, l0, h1, l1;
        __nv_bfloat162 hv, lv;
        bsplit(yA0, h0, l0); bsplit(yA1, h1, l1);
        hv.x = h0; hv.y = h1; lv.x = l0; lv.y = l1;
        *(__nv_bfloat162*)(g_Yhi + baseA + col) = hv;
        *(__nv_bfloat162*)(g_Ylo + baseA + col) = lv;
        bsplit(yB0, h0, l0); bsplit(yB1, h1, l1);
        hv.x = h0; hv.y = h1; lv.x = l0; lv.y = l1;
        *(__nv_bfloat162*)(g_Yhi + baseB + col) = hv;
        *(__nv_bfloat162*)(g_Ylo + baseB + col) = lv;
    }
}

// ---------------------------------------------------------------------------
// Launch
// ---------------------------------------------------------------------------
extern "C" void kernel_launch(void* const* d_in, const int* in_sizes, int n_in,
                              void* d_out, int out_size)
{
    const float* x      = (const float*)d_in[0];
    const float* w_attn = (const float*)d_in[1];
    const float* b_attn = (const float*)d_in[2];
    const float* w_proj = (const float*)d_in[3];
    const float* b_proj = (const float*)d_in[4];
    float* out = (float*)d_out;

    // 0) Transpose + split weights; split x
    {
        dim3 blk(32, 8);
        transpose_split_kernel<0><<<dim3(3 * CDIM / 32, KDIM / 32), blk>>>(w_attn, 3 * CDIM);
        transpose_split_kernel<1><<<dim3(CDIM / 32, KDIM / 32), blk>>>(w_proj, CDIM);
        split_kernel<<<(MROWS * KDIM) / (256 * 4), 256>>>(x);
    }

    // 1) QKV GEMM (3xbf16) -> pre-split Q/K + transposed V
    {
        cudaFuncSetAttribute(tc_gemm<3 * CDIM, 0>,
                             cudaFuncAttributeMaxDynamicSharedMemorySize, GSMEM);
        dim3 grid(3 * CDIM / GBN, MROWS / GBM);   // (24, 32)
        tc_gemm<3 * CDIM, 0><<<grid, 256, GSMEM>>>(b_attn, nullptr);
    }

    // 2) Tensor-core flash attention (3xbf16) -> pre-split Y
    {
        cudaFuncSetAttribute(attn_kernel,
                             cudaFuncAttributeMaxDynamicSharedMemorySize, ASMEM);
        dim3 grid(TSEQ / ABQ, NB * NH);           // (8, 64)
        attn_kernel<<<grid, 256, ASMEM>>>();
    }

    // 3) Output projection (3xbf16)
    {
        cudaFuncSetAttribute(tc_gemm<CDIM, 1>,
                             cudaFuncAttributeMaxDynamicSharedMemorySize, GSMEM);
        dim3 grid(CDIM / GBN, MROWS / GBM);       // (8, 32)
        tc_gemm<CDIM, 1><<<grid, 256, GSMEM>>>(b_proj, out);
    }
}

// round 8
// speedup vs baseline: 3.3366x; 1.0897x over previous
#include <cuda_runtime.h>
#include <cuda_bf16.h>
#include <math.h>
#include <stdint.h>

// Problem constants
#define NB    4
#define TSEQ  1024
#define CDIM  1024
#define NH    16
#define DH    64
#define MROWS (NB * TSEQ)      // 4096
#define KDIM  1024

// Scratch (device globals -- no allocation allowed)
__device__ __nv_bfloat16 g_Xhi[(size_t)MROWS * KDIM];
__device__ __nv_bfloat16 g_Xlo[(size_t)MROWS * KDIM];
__device__ __nv_bfloat16 g_Yhi[(size_t)MROWS * KDIM];
__device__ __nv_bfloat16 g_Ylo[(size_t)MROWS * KDIM];
__device__ __nv_bfloat16 g_WAhi[(size_t)3 * CDIM * KDIM];   // w_attn^T [n][k]
__device__ __nv_bfloat16 g_WAlo[(size_t)3 * CDIM * KDIM];
__device__ __nv_bfloat16 g_WPhi[(size_t)CDIM * KDIM];       // w_proj^T [n][k]
__device__ __nv_bfloat16 g_WPlo[(size_t)CDIM * KDIM];
__device__ __nv_bfloat16 g_Qh[(size_t)NB * NH * TSEQ * DH];
__device__ __nv_bfloat16 g_Qlo[(size_t)NB * NH * TSEQ * DH];
__device__ __nv_bfloat16 g_Kh[(size_t)NB * NH * TSEQ * DH];
__device__ __nv_bfloat16 g_Klo[(size_t)NB * NH * TSEQ * DH];
__device__ __nv_bfloat16 g_Vth[(size_t)NB * NH * DH * TSEQ];
__device__ __nv_bfloat16 g_Vtl[(size_t)NB * NH * DH * TSEQ];

// ---------------------------------------------------------------------------
// Helpers
// ---------------------------------------------------------------------------
__device__ __forceinline__ uint32_t smem_u32(const void* p) {
    return (uint32_t)__cvta_generic_to_shared(p);
}

__device__ __forceinline__ void cp_async16(uint32_t saddr, const void* gptr) {
    asm volatile("cp.async.cg.shared.global [%0], [%1], 16;" :: "r"(saddr), "l"(gptr));
}
#define CP_COMMIT() asm volatile("cp.async.commit_group;" ::: "memory")

__device__ __forceinline__ void ldsm_x4(uint32_t* r, uint32_t addr) {
    asm volatile("ldmatrix.sync.aligned.m8n8.x4.shared.b16 {%0,%1,%2,%3}, [%4];"
                 : "=r"(r[0]), "=r"(r[1]), "=r"(r[2]), "=r"(r[3]) : "r"(addr));
}

__device__ __forceinline__ void mma_bf16(float* c, const uint32_t* a,
                                         uint32_t b0, uint32_t b1) {
    asm volatile(
        "mma.sync.aligned.m16n8k16.row.col.f32.bf16.bf16.f32 "
        "{%0,%1,%2,%3}, {%4,%5,%6,%7}, {%8,%9}, {%0,%1,%2,%3};"
        : "+f"(c[0]), "+f"(c[1]), "+f"(c[2]), "+f"(c[3])
        : "r"(a[0]), "r"(a[1]), "r"(a[2]), "r"(a[3]), "r"(b0), "r"(b1));
}

__device__ __forceinline__ void bsplit(float f, __nv_bfloat16& h, __nv_bfloat16& l) {
    h = __float2bfloat16_rn(f);
    l = __float2bfloat16_rn(f - __bfloat162float(h));
}

__device__ __forceinline__ float fast_exp2(float x) {
    float r;
    asm("ex2.approx.ftz.f32 %0, %1;" : "=f"(r) : "f"(x));
    return r;
}

// ---------------------------------------------------------------------------
// Weight transpose + bf16 split: src [KDIM][cols] -> hi/lo [cols][KDIM]
// ---------------------------------------------------------------------------
template <int WHICH>
__global__ __launch_bounds__(256) void transpose_split_kernel(const float* __restrict__ src,
                                                              int cols)
{
    __shared__ float tile[32][33];
    __nv_bfloat16* dh = WHICH ? g_WPhi : g_WAhi;
    __nv_bfloat16* dl = WHICH ? g_WPlo : g_WAlo;
    const int c0 = blockIdx.x * 32;
    const int r0 = blockIdx.y * 32;
    const int tx = threadIdx.x, ty = threadIdx.y;   // (32, 8)
#pragma unroll
    for (int j = 0; j < 32; j += 8)
        tile[ty + j][tx] = src[(size_t)(r0 + ty + j) * cols + c0 + tx];
    __syncthreads();
#pragma unroll
    for (int j = 0; j < 32; j += 8) {
        float f = tile[tx][ty + j];
        __nv_bfloat16 h, l;
        bsplit(f, h, l);
        size_t o = (size_t)(c0 + ty + j) * KDIM + r0 + tx;
        dh[o] = h;
        dl[o] = l;
    }
}

// ---------------------------------------------------------------------------
// Activation bf16 split for x -> g_Xhi/lo
// ---------------------------------------------------------------------------
__global__ __launch_bounds__(256) void split_kernel(const float* __restrict__ xin)
{
    size_t i = ((size_t)blockIdx.x * 256 + threadIdx.x) * 4;
    float4 v = *(const float4*)(xin + i);
    __nv_bfloat16 h0, l0, h1, l1, h2, l2, h3, l3;
    bsplit(v.x, h0, l0); bsplit(v.y, h1, l1);
    bsplit(v.z, h2, l2); bsplit(v.w, h3, l3);
    __nv_bfloat162* ph = (__nv_bfloat162*)(g_Xhi + i);
    __nv_bfloat162* pl = (__nv_bfloat162*)(g_Xlo + i);
    __nv_bfloat162 a; a.x = h0; a.y = h1;
    __nv_bfloat162 b; b.x = h2; b.y = h3;
    ph[0] = a; ph[1] = b;
    a.x = l0; a.y = l1; b.x = l2; b.y = l3;
    pl[0] = a; pl[1] = b;
}

// ---------------------------------------------------------------------------
// 3xBF16 mma.sync GEMM. BK=32 (64B rows, chunk^=(row>>1)&3 swizzle),
// 3 stages = 96KB smem -> 2 CTAs/SM.
// MODE0: QKV -> pre-split bf16 Q/K ([bh][t][d]) and V^T ([bh][d][t])
// MODE1: proj -> out fp32 [m][n]
// ---------------------------------------------------------------------------
#define GBM 128
#define GBN 128
#define GBK 32
#define KTILES  (KDIM / GBK)            // 32
#define PANEL   8192                     // 128 rows x 64 B
#define STAGE   (4 * PANEL)              // AH, AL, BH, BL = 32768
#define GSMEM   (3 * STAGE)              // 98304
#define OAH 0
#define OAL 8192
#define OBH 16384
#define OBL 24576

__device__ __forceinline__ uint32_t sw64(int row, int ch) {
    return (uint32_t)row * 64 + (uint32_t)((ch ^ ((row >> 1) & 3)) << 4);
}

__device__ __forceinline__ void load_tile_b(uint32_t sg,
        const __nv_bfloat16* Ah, const __nv_bfloat16* Al,
        const __nv_bfloat16* Bh, const __nv_bfloat16* Bl,
        int k0, int tid)
{
#pragma unroll
    for (int l = 0; l < 8; l++) {
        int idx = tid + l * 256;          // 0..2047
        int panel = idx >> 9;             // 0..3
        int rem = idx & 511;
        int row = rem >> 2;               // 0..127
        int ch  = rem & 3;                // 16B chunk along k (8 bf16)
        uint32_t sw = sw64(row, ch);
        const size_t g = (size_t)row * KDIM + k0 + ch * 8;
        const __nv_bfloat16* src = (panel == 0) ? Ah : (panel == 1) ? Al
                                  : (panel == 2) ? Bh : Bl;
        cp_async16(sg + (uint32_t)panel * PANEL + sw, src + g);
    }
}

template <int N, int MODE>
__global__ __launch_bounds__(256, 2) void tc_gemm(const float* __restrict__ bias,
                                                  float* __restrict__ out)
{
    extern __shared__ char smem[];
    const uint32_t sbase = smem_u32(smem);
    const int tid  = threadIdx.x;
    const int warp = tid >> 5;
    const int lane = tid & 31;
    const int wm = warp >> 1;             // 0..3
    const int wn = warp & 1;              // 0..1
    const int bm = blockIdx.y * GBM;
    const int bn = blockIdx.x * GBN;

    const __nv_bfloat16* Ah = ((MODE == 0) ? g_Xhi : g_Yhi) + (size_t)bm * KDIM;
    const __nv_bfloat16* Al = ((MODE == 0) ? g_Xlo : g_Ylo) + (size_t)bm * KDIM;
    const __nv_bfloat16* Bh = ((MODE == 0) ? g_WAhi : g_WPhi) + (size_t)bn * KDIM;
    const __nv_bfloat16* Bl = ((MODE == 0) ? g_WAlo : g_WPlo) + (size_t)bn * KDIM;

    const int arow = wm * 32 + (lane & 15);            // + mi*16
    const int acb = (lane >> 4) & 1;
    const int brow = wn * 64 + (lane & 7) + ((lane & 16) >> 1);  // + pi*16
    const int bcb = (lane >> 3) & 1;

    float acc[2][8][4];
#pragma unroll
    for (int mi = 0; mi < 2; mi++)
#pragma unroll
        for (int ni = 0; ni < 8; ni++)
#pragma unroll
            for (int r = 0; r < 4; r++) acc[mi][ni][r] = 0.0f;

#pragma unroll
    for (int t = 0; t < 2; t++) {
        load_tile_b(sbase + t * STAGE, Ah, Al, Bh, Bl, t * GBK, tid);
        CP_COMMIT();
    }

    for (int t = 0; t < KTILES; t++) {
        if (t < KTILES - 2)
            asm volatile("cp.async.wait_group 1;" ::: "memory");
        else
            asm volatile("cp.async.wait_group 0;" ::: "memory");
        __syncthreads();

        const uint32_t sg = sbase + (uint32_t)(t % 3) * STAGE;

#pragma unroll
        for (int ks = 0; ks < 2; ks++) {    // k16 steps over BK=32
            uint32_t ah[2][4], al[2][4], bh[4][4], bl[4][4];
#pragma unroll
            for (int mi = 0; mi < 2; mi++) {
                uint32_t ao = sw64(arow + mi * 16, ks * 2 + acb);
                ldsm_x4(ah[mi], sg + OAH + ao);
                ldsm_x4(al[mi], sg + OAL + ao);
            }
#pragma unroll
            for (int pi = 0; pi < 4; pi++) {
                uint32_t bo = sw64(brow + pi * 16, ks * 2 + bcb);
                ldsm_x4(bh[pi], sg + OBH + bo);
                ldsm_x4(bl[pi], sg + OBL + bo);
            }
#pragma unroll
            for (int mi = 0; mi < 2; mi++)
#pragma unroll
                for (int ni = 0; ni < 8; ni++) {
                    const int pi = ni >> 1;
                    const int j0 = (ni & 1) * 2;
                    mma_bf16(acc[mi][ni], al[mi], bh[pi][j0], bh[pi][j0 + 1]);
                    mma_bf16(acc[mi][ni], ah[mi], bl[pi][j0], bl[pi][j0 + 1]);
                    mma_bf16(acc[mi][ni], ah[mi], bh[pi][j0], bh[pi][j0 + 1]);
                }
        }

        if (t + 2 < KTILES) {
            load_tile_b(sbase + (uint32_t)((t + 2) % 3) * STAGE,
                        Ah, Al, Bh, Bl, (t + 2) * GBK, tid);
            CP_COMMIT();
        }
    }

    // Epilogue
#pragma unroll
    for (int mi = 0; mi < 2; mi++) {
#pragma unroll
        for (int ni = 0; ni < 8; ni++) {
            const int col = bn + wn * 64 + ni * 8 + (lane & 3) * 2;
            float2 bv = *(const float2*)(bias + col);
#pragma unroll
            for (int half = 0; half < 2; half++) {
                const int row = bm + wm * 32 + mi * 16 + (lane >> 2) + half * 8;
                float vx = acc[mi][ni][half * 2 + 0] + bv.x;
                float vy = acc[mi][ni][half * 2 + 1] + bv.y;
                if (MODE == 0) {
                    const int sec  = col >> 10;          // 0=q, 1=k, 2=v
                    const int cc   = col & 1023;
                    const int head = cc >> 6;
                    const int dpos = cc & 63;
                    const int b  = row >> 10;
                    const int tt = row & 1023;
                    const int bh2 = b * NH + head;
                    __nv_bfloat16 hx, lx, hy, ly;
                    bsplit(vx, hx, lx); bsplit(vy, hy, ly);
                    if (sec < 2) {
                        size_t o = ((size_t)bh2 * TSEQ + tt) * DH + dpos;
                        __nv_bfloat162 hv; hv.x = hx; hv.y = hy;
                        __nv_bfloat162 lv; lv.x = lx; lv.y = ly;
                        if (sec == 0) {
                            *(__nv_bfloat162*)(g_Qh + o) = hv;
                            *(__nv_bfloat162*)(g_Qlo + o) = lv;
                        } else {
                            *(__nv_bfloat162*)(g_Kh + o) = hv;
                            *(__nv_bfloat162*)(g_Klo + o) = lv;
                        }
                    } else {
                        size_t o0 = ((size_t)bh2 * DH + dpos) * TSEQ + tt;
                        g_Vth[o0] = hx; g_Vtl[o0] = lx;
                        g_Vth[o0 + TSEQ] = hy; g_Vtl[o0 + TSEQ] = ly;
                    }
                } else {
                    float2 v2; v2.x = vx; v2.y = vy;
                    *(float2*)(out + (size_t)row * N + col) = v2;
                }
            }
        }
    }
}

// ---------------------------------------------------------------------------
// Tensor-core flash attention, 3xBF16, pre-split operands (unchanged except
// qi remap: heavy tiles launch first for better tail packing).
// ---------------------------------------------------------------------------
#define ABQ   128
#define ABK   64
#define SQH 0
#define SQL 16384
#define SKH 32768
#define SKL 40960
#define SVH 49152
#define SVL 57344
#define SPH 65536
#define SPL 81920
#define ASMEM 98304

__global__ __launch_bounds__(256, 2) void attn_kernel()
{
    extern __shared__ char smc[];
    const uint32_t sb = smem_u32(smc);

    const int qi = gridDim.x - 1 - blockIdx.x;   // heavy tiles first
    const int bh = blockIdx.y;
    const int bb = bh >> 4, hh = bh & 15;
    const __nv_bfloat16* Qhp = g_Qh  + (size_t)bh * TSEQ * DH;
    const __nv_bfloat16* Qlp = g_Qlo + (size_t)bh * TSEQ * DH;
    const __nv_bfloat16* Khp = g_Kh  + (size_t)bh * TSEQ * DH;
    const __nv_bfloat16* Klp = g_Klo + (size_t)bh * TSEQ * DH;
    const __nv_bfloat16* Vhp = g_Vth + (size_t)bh * DH * TSEQ;
    const __nv_bfloat16* Vlp = g_Vtl + (size_t)bh * DH * TSEQ;

    const int tid  = threadIdx.x;
    const int warp = tid >> 5;
    const int lane = tid & 31;
    const int rA   = lane >> 2;
    const int qcol = (lane & 3) * 2;

    const int acb  = (lane >> 4) & 1;
    const int bcb  = (lane >> 3) & 1;
    const int brow = (lane & 7) + ((lane & 16) >> 1);

    // Q panels: 128 rows x 128 B, hi+lo (committed with first K/V group)
#pragma unroll
    for (int l = 0; l < 8; l++) {
        int idx = tid + l * 256;
        int panel = idx >> 10;
        int rem = idx & 1023;
        int r = rem >> 3, ch = rem & 7;
        uint32_t off = (uint32_t)r * 128 + ch * 16;
        uint32_t sw = off ^ ((off >> 3) & 0x70);
        const __nv_bfloat16* src = (panel ? Qlp : Qhp) + (size_t)(qi * ABQ + r) * DH + ch * 8;
        cp_async16(sb + (panel ? SQL : SQH) + sw, src);
    }

    float o[8][4];
#pragma unroll
    for (int ni = 0; ni < 8; ni++)
#pragma unroll
        for (int j = 0; j < 4; j++) o[ni][j] = 0.0f;
    float mA = -1e30f, mB = -1e30f, lAcc = 0.0f, lBcc = 0.0f;

    const float CS = 0.18033688011112042f;   // 0.125 * log2(e)
    const int ntiles = 2 * qi + 2;

    for (int kt = 0; kt < ntiles; kt++) {
        __syncthreads();
#pragma unroll
        for (int l = 0; l < 4; l++) {
            int idx = tid + l * 256;
            int panel = idx >> 9;
            int rem = idx & 511;
            int r = rem >> 3, ch = rem & 7;
            uint32_t off = (uint32_t)r * 128 + ch * 16;
            uint32_t sw = off ^ ((off >> 3) & 0x70);
            cp_async16(sb + (panel ? SKL : SKH) + sw,
                       (panel ? Klp : Khp) + (size_t)(kt * ABK + r) * DH + ch * 8);
            cp_async16(sb + (panel ? SVL : SVH) + sw,
                       (panel ? Vlp : Vhp) + (size_t)r * TSEQ + kt * ABK + ch * 8);
        }
        CP_COMMIT();
        asm volatile("cp.async.wait_group 0;" ::: "memory");
        __syncthreads();

        if (kt * ABK <= qi * ABQ + warp * 16 + 15) {
            // ---- S = Q K^T (3xbf16) ----
            float s[8][4];
#pragma unroll
            for (int ni = 0; ni < 8; ni++)
#pragma unroll
                for (int j = 0; j < 4; j++) s[ni][j] = 0.0f;

            const int aQrow = warp * 16 + (lane & 15);
            const uint32_t a_ro = (uint32_t)aQrow * 128;
            const int a_rx = aQrow & 7;
#pragma unroll
            for (int ks = 0; ks < 4; ks++) {
                uint32_t ah[4], al[4], kh[4][4], kl[4][4];
                uint32_t ao = a_ro + (uint32_t)(((ks * 2 + acb) ^ a_rx) << 4);
                ldsm_x4(ah, sb + SQH + ao);
                ldsm_x4(al, sb + SQL + ao);
#pragma unroll
                for (int pi = 0; pi < 4; pi++) {
                    int br = pi * 16 + brow;
                    uint32_t bo = (uint32_t)br * 128 +
                                  (uint32_t)(((ks * 2 + bcb) ^ (br & 7)) << 4);
                    ldsm_x4(kh[pi], sb + SKH + bo);
                    ldsm_x4(kl[pi], sb + SKL + bo);
                }
#pragma unroll
                for (int ni = 0; ni < 8; ni++) {
                    const int pi = ni >> 1, j0 = (ni & 1) * 2;
                    mma_bf16(s[ni], al, kh[pi][j0], kh[pi][j0 + 1]);
                    mma_bf16(s[ni], ah, kl[pi][j0], kl[pi][j0 + 1]);
                    mma_bf16(s[ni], ah, kh[pi][j0], kh[pi][j0 + 1]);
                }
            }

            // ---- scale + causal mask ----
            const bool needmask = (kt * ABK + ABK - 1 > qi * ABQ + warp * 16);
            const int rowgA = qi * ABQ + warp * 16 + rA;
            const int rowgB = rowgA + 8;
            const int cb = kt * ABK + qcol;
#pragma unroll
            for (int ni = 0; ni < 8; ni++) {
                float z0 = s[ni][0] * CS, z1 = s[ni][1] * CS;
                float z2 = s[ni][2] * CS, z3 = s[ni][3] * CS;
                if (needmask) {
                    int c0 = cb + ni * 8, c1 = c0 + 1;
                    if (c0 > rowgA) z0 = -1e30f;
                    if (c1 > rowgA) z1 = -1e30f;
                    if (c0 > rowgB) z2 = -1e30f;
                    if (c1 > rowgB) z3 = -1e30f;
                }
                s[ni][0] = z0; s[ni][1] = z1; s[ni][2] = z2; s[ni][3] = z3;
            }

            // ---- online softmax ----
            float mtA = -1e30f, mtB = -1e30f;
#pragma unroll
            for (int ni = 0; ni < 8; ni++) {
                mtA = fmaxf(mtA, fmaxf(s[ni][0], s[ni][1]));
                mtB = fmaxf(mtB, fmaxf(s[ni][2], s[ni][3]));
            }
            mtA = fmaxf(mtA, __shfl_xor_sync(0xffffffffu, mtA, 1));
            mtA = fmaxf(mtA, __shfl_xor_sync(0xffffffffu, mtA, 2));
            mtB = fmaxf(mtB, __shfl_xor_sync(0xffffffffu, mtB, 1));
            mtB = fmaxf(mtB, __shfl_xor_sync(0xffffffffu, mtB, 2));

            const float mnA = fmaxf(mA, mtA);
            const float mnB = fmaxf(mB, mtB);
            const float aAl = fast_exp2(mA - mnA);
            const float aBl = fast_exp2(mB - mnB);
            mA = mnA; mB = mnB;

            float psA = 0.0f, psB = 0.0f;
#pragma unroll
            for (int ni = 0; ni < 8; ni++) {
                float p0 = fast_exp2(s[ni][0] - mnA);
                float p1 = fast_exp2(s[ni][1] - mnA);
                float p2 = fast_exp2(s[ni][2] - mnB);
                float p3 = fast_exp2(s[ni][3] - mnB);
                psA += p0 + p1; psB += p2 + p3;
                s[ni][0] = p0; s[ni][1] = p1; s[ni][2] = p2; s[ni][3] = p3;
            }
            psA += __shfl_xor_sync(0xffffffffu, psA, 1);
            psA += __shfl_xor_sync(0xffffffffu, psA, 2);
            psB += __shfl_xor_sync(0xffffffffu, psB, 1);
            psB += __shfl_xor_sync(0xffffffffu, psB, 2);
            lAcc = lAcc * aAl + psA;
            lBcc = lBcc * aBl + psB;

#pragma unroll
            for (int ni = 0; ni < 8; ni++) {
                o[ni][0] *= aAl; o[ni][1] *= aAl;
                o[ni][2] *= aBl; o[ni][3] *= aBl;
            }

            // ---- store P (bf16 hi/lo) to warp-private panel rows ----
#pragma unroll
            for (int ni = 0; ni < 8; ni++) {
                int col = ni * 8 + qcol;
                __nv_bfloat16 h0, l0, h1, l1, h2, l2, h3, l3;
                bsplit(s[ni][0], h0, l0); bsplit(s[ni][1], h1, l1);
                bsplit(s[ni][2], h2, l2); bsplit(s[ni][3], h3, l3);
                int r0 = warp * 16 + rA, r1 = r0 + 8;
                uint32_t off0 = (uint32_t)r0 * 128 + col * 2;
                uint32_t off1 = (uint32_t)r1 * 128 + col * 2;
                uint32_t sw0 = off0 ^ ((off0 >> 3) & 0x70);
                uint32_t sw1 = off1 ^ ((off1 >> 3) & 0x70);
                __nv_bfloat162 hv, lv;
                hv.x = h0; hv.y = h1; lv.x = l0; lv.y = l1;
                *(__nv_bfloat162*)(smc + SPH + sw0) = hv;
                *(__nv_bfloat162*)(smc + SPL + sw0) = lv;
                hv.x = h2; hv.y = h3; lv.x = l2; lv.y = l3;
                *(__nv_bfloat162*)(smc + SPH + sw1) = hv;
                *(__nv_bfloat162*)(smc + SPL + sw1) = lv;
            }
            __syncwarp();

            // ---- O += P V (3xbf16) ----
            const int aProw = warp * 16 + (lane & 15);
            const uint32_t p_ro = (uint32_t)aProw * 128;
            const int p_rx = aProw & 7;
#pragma unroll
            for (int ks = 0; ks < 4; ks++) {
                uint32_t ph[4], pl[4], vh[4][4], vl[4][4];
                uint32_t ao = p_ro + (uint32_t)(((ks * 2 + acb) ^ p_rx) << 4);
                ldsm_x4(ph, sb + SPH + ao);
                ldsm_x4(pl, sb + SPL + ao);
#pragma unroll
                for (int pi = 0; pi < 4; pi++) {
                    int br = pi * 16 + brow;
                    uint32_t bo = (uint32_t)br * 128 +
                                  (uint32_t)(((ks * 2 + bcb) ^ (br & 7)) << 4);
                    ldsm_x4(vh[pi], sb + SVH + bo);
                    ldsm_x4(vl[pi], sb + SVL + bo);
                }
#pragma unroll
                for (int ni = 0; ni < 8; ni++) {
                    const int pi = ni >> 1, j0 = (ni & 1) * 2;
                    mma_bf16(o[ni], pl, vh[pi][j0], vh[pi][j0 + 1]);
                    mma_bf16(o[ni], ph, vl[pi][j0], vl[pi][j0 + 1]);
                    mma_bf16(o[ni], ph, vh[pi][j0], vh[pi][j0 + 1]);
                }
            }
        }
    }

    // ---- epilogue: normalize, split to bf16, write g_Yhi/lo [b][t][c] ----
    const float invA = 1.0f / lAcc;
    const float invB = 1.0f / lBcc;
    const int tA = qi * ABQ + warp * 16 + rA;
    const int tB = tA + 8;
    const size_t baseA = ((size_t)bb * TSEQ + tA) * CDIM + hh * DH;
    const size_t baseB = ((size_t)bb * TSEQ + tB) * CDIM + hh * DH;
#pragma unroll
    for (int ni = 0; ni < 8; ni++) {
        int col = ni * 8 + qcol;
        float yA0 = o[ni][0] * invA, yA1 = o[ni][1] * invA;
        float yB0 = o[ni][2] * invB, yB1 = o[ni][3] * invB;
        __nv_bfloat16 h0, l0, h1, l1;
        __nv_bfloat162 hv, lv;
        bsplit(yA0, h0, l0); bsplit(yA1, h1, l1);
        hv.x = h0; hv.y = h1; lv.x = l0; lv.y = l1;
        *(__nv_bfloat162*)(g_Yhi + baseA + col) = hv;
        *(__nv_bfloat162*)(g_Ylo + baseA + col) = lv;
        bsplit(yB0, h0, l0); bsplit(yB1, h1, l1);
        hv.x = h0; hv.y = h1; lv.x = l0; lv.y = l1;
        *(__nv_bfloat162*)(g_Yhi + baseB + col) = hv;
        *(__nv_bfloat162*)(g_Ylo + baseB + col) = lv;
    }
}

// ---------------------------------------------------------------------------
// Launch
// ---------------------------------------------------------------------------
extern "C" void kernel_launch(void* const* d_in, const int* in_sizes, int n_in,
                              void* d_out, int out_size)
{
    const float* x      = (const float*)d_in[0];
    const float* w_attn = (const float*)d_in[1];
    const float* b_attn = (const float*)d_in[2];
    const float* w_proj = (const float*)d_in[3];
    const float* b_proj = (const float*)d_in[4];
    float* out = (float*)d_out;

    // 0) Transpose + split weights; split x
    {
        dim3 blk(32, 8);
        transpose_split_kernel<0><<<dim3(3 * CDIM / 32, KDIM / 32), blk>>>(w_attn, 3 * CDIM);
        transpose_split_kernel<1><<<dim3(CDIM / 32, KDIM / 32), blk>>>(w_proj, CDIM);
        split_kernel<<<(MROWS * KDIM) / (256 * 4), 256>>>(x);
    }

    // 1) QKV GEMM (3xbf16) -> pre-split Q/K + transposed V
    {
        cudaFuncSetAttribute(tc_gemm<3 * CDIM, 0>,
                             cudaFuncAttributeMaxDynamicSharedMemorySize, GSMEM);
        dim3 grid(3 * CDIM / GBN, MROWS / GBM);   // (24, 32)
        tc_gemm<3 * CDIM, 0><<<grid, 256, GSMEM>>>(b_attn, nullptr);
    }

    // 2) Tensor-core flash attention (3xbf16) -> pre-split Y
    {
        cudaFuncSetAttribute(attn_kernel,
                             cudaFuncAttributeMaxDynamicSharedMemorySize, ASMEM);
        dim3 grid(TSEQ / ABQ, NB * NH);           // (8, 64)
        attn_kernel<<<grid, 256, ASMEM>>>();
    }

    // 3) Output projection (3xbf16)
    {
        cudaFuncSetAttribute(tc_gemm<CDIM, 1>,
                             cudaFuncAttributeMaxDynamicSharedMemorySize, GSMEM);
        dim3 grid(CDIM / GBN, MROWS / GBM);       // (8, 32)
        tc_gemm<CDIM, 1><<<grid, 256, GSMEM>>>(b_proj, out);
    }
}

// round 9
// speedup vs baseline: 3.3851x; 1.0146x over previous
#include <cuda_runtime.h>
#include <cuda_bf16.h>
#include <math.h>
#include <stdint.h>

// Problem constants
#define NB    4
#define TSEQ  1024
#define CDIM  1024
#define NH    16
#define DH    64
#define MROWS (NB * TSEQ)      // 4096
#define KDIM  1024

// Scratch (device globals -- no allocation allowed)
__device__ __nv_bfloat16 g_Xhi[(size_t)MROWS * KDIM];
__device__ __nv_bfloat16 g_Xlo[(size_t)MROWS * KDIM];
__device__ __nv_bfloat16 g_Yhi[(size_t)MROWS * KDIM];
__device__ __nv_bfloat16 g_Ylo[(size_t)MROWS * KDIM];
__device__ __nv_bfloat16 g_WAhi[(size_t)3 * CDIM * KDIM];   // w_attn^T [n][k]
__device__ __nv_bfloat16 g_WAlo[(size_t)3 * CDIM * KDIM];
__device__ __nv_bfloat16 g_WPhi[(size_t)CDIM * KDIM];       // w_proj^T [n][k]
__device__ __nv_bfloat16 g_WPlo[(size_t)CDIM * KDIM];
__device__ __nv_bfloat16 g_Qh[(size_t)NB * NH * TSEQ * DH];
__device__ __nv_bfloat16 g_Qlo[(size_t)NB * NH * TSEQ * DH];
__device__ __nv_bfloat16 g_Kh[(size_t)NB * NH * TSEQ * DH];
__device__ __nv_bfloat16 g_Klo[(size_t)NB * NH * TSEQ * DH];
__device__ __nv_bfloat16 g_Vth[(size_t)NB * NH * DH * TSEQ];
__device__ __nv_bfloat16 g_Vtl[(size_t)NB * NH * DH * TSEQ];

// ---------------------------------------------------------------------------
// Helpers
// ---------------------------------------------------------------------------
__device__ __forceinline__ uint32_t smem_u32(const void* p) {
    return (uint32_t)__cvta_generic_to_shared(p);
}

__device__ __forceinline__ void cp_async16(uint32_t saddr, const void* gptr) {
    asm volatile("cp.async.cg.shared.global [%0], [%1], 16;" :: "r"(saddr), "l"(gptr));
}
#define CP_COMMIT() asm volatile("cp.async.commit_group;" ::: "memory")

__device__ __forceinline__ void ldsm_x4(uint32_t* r, uint32_t addr) {
    asm volatile("ldmatrix.sync.aligned.m8n8.x4.shared.b16 {%0,%1,%2,%3}, [%4];"
                 : "=r"(r[0]), "=r"(r[1]), "=r"(r[2]), "=r"(r[3]) : "r"(addr));
}

__device__ __forceinline__ void mma_bf16(float* c, const uint32_t* a,
                                         uint32_t b0, uint32_t b1) {
    asm volatile(
        "mma.sync.aligned.m16n8k16.row.col.f32.bf16.bf16.f32 "
        "{%0,%1,%2,%3}, {%4,%5,%6,%7}, {%8,%9}, {%0,%1,%2,%3};"
        : "+f"(c[0]), "+f"(c[1]), "+f"(c[2]), "+f"(c[3])
        : "r"(a[0]), "r"(a[1]), "r"(a[2]), "r"(a[3]), "r"(b0), "r"(b1));
}

__device__ __forceinline__ void bsplit(float f, __nv_bfloat16& h, __nv_bfloat16& l) {
    h = __float2bfloat16_rn(f);
    l = __float2bfloat16_rn(f - __bfloat162float(h));
}

__device__ __forceinline__ float fast_exp2(float x) {
    float r;
    asm("ex2.approx.ftz.f32 %0, %1;" : "=f"(r) : "f"(x));
    return r;
}

// ---------------------------------------------------------------------------
// Weight transpose + bf16 split: src [KDIM][cols] -> hi/lo [cols][KDIM]
// ---------------------------------------------------------------------------
template <int WHICH>
__global__ __launch_bounds__(256) void transpose_split_kernel(const float* __restrict__ src,
                                                              int cols)
{
    __shared__ float tile[32][33];
    __nv_bfloat16* dh = WHICH ? g_WPhi : g_WAhi;
    __nv_bfloat16* dl = WHICH ? g_WPlo : g_WAlo;
    const int c0 = blockIdx.x * 32;
    const int r0 = blockIdx.y * 32;
    const int tx = threadIdx.x, ty = threadIdx.y;   // (32, 8)
#pragma unroll
    for (int j = 0; j < 32; j += 8)
        tile[ty + j][tx] = src[(size_t)(r0 + ty + j) * cols + c0 + tx];
    __syncthreads();
#pragma unroll
    for (int j = 0; j < 32; j += 8) {
        float f = tile[tx][ty + j];
        __nv_bfloat16 h, l;
        bsplit(f, h, l);
        size_t o = (size_t)(c0 + ty + j) * KDIM + r0 + tx;
        dh[o] = h;
        dl[o] = l;
    }
}

// ---------------------------------------------------------------------------
// Activation bf16 split for x -> g_Xhi/lo
// ---------------------------------------------------------------------------
__global__ __launch_bounds__(256) void split_kernel(const float* __restrict__ xin)
{
    size_t i = ((size_t)blockIdx.x * 256 + threadIdx.x) * 4;
    float4 v = *(const float4*)(xin + i);
    __nv_bfloat16 h0, l0, h1, l1, h2, l2, h3, l3;
    bsplit(v.x, h0, l0); bsplit(v.y, h1, l1);
    bsplit(v.z, h2, l2); bsplit(v.w, h3, l3);
    __nv_bfloat162* ph = (__nv_bfloat162*)(g_Xhi + i);
    __nv_bfloat162* pl = (__nv_bfloat162*)(g_Xlo + i);
    __nv_bfloat162 a; a.x = h0; a.y = h1;
    __nv_bfloat162 b; b.x = h2; b.y = h3;
    ph[0] = a; ph[1] = b;
    a.x = l0; a.y = l1; b.x = l2; b.y = l3;
    pl[0] = a; pl[1] = b;
}

// ---------------------------------------------------------------------------
// 3xBF16 mma.sync GEMM (unchanged from R8). BK=32, 3 stages, 2 CTAs/SM.
// ---------------------------------------------------------------------------
#define GBM 128
#define GBN 128
#define GBK 32
#define KTILES  (KDIM / GBK)            // 32
#define PANEL   8192                     // 128 rows x 64 B
#define STAGE   (4 * PANEL)              // AH, AL, BH, BL = 32768
#define GSMEM   (3 * STAGE)              // 98304
#define OAH 0
#define OAL 8192
#define OBH 16384
#define OBL 24576

__device__ __forceinline__ uint32_t sw64(int row, int ch) {
    return (uint32_t)row * 64 + (uint32_t)((ch ^ ((row >> 1) & 3)) << 4);
}

__device__ __forceinline__ void load_tile_b(uint32_t sg,
        const __nv_bfloat16* Ah, const __nv_bfloat16* Al,
        const __nv_bfloat16* Bh, const __nv_bfloat16* Bl,
        int k0, int tid)
{
#pragma unroll
    for (int l = 0; l < 8; l++) {
        int idx = tid + l * 256;          // 0..2047
        int panel = idx >> 9;             // 0..3
        int rem = idx & 511;
        int row = rem >> 2;               // 0..127
        int ch  = rem & 3;                // 16B chunk along k (8 bf16)
        uint32_t sw = sw64(row, ch);
        const size_t g = (size_t)row * KDIM + k0 + ch * 8;
        const __nv_bfloat16* src = (panel == 0) ? Ah : (panel == 1) ? Al
                                  : (panel == 2) ? Bh : Bl;
        cp_async16(sg + (uint32_t)panel * PANEL + sw, src + g);
    }
}

template <int N, int MODE>
__global__ __launch_bounds__(256, 2) void tc_gemm(const float* __restrict__ bias,
                                                  float* __restrict__ out)
{
    extern __shared__ char smem[];
    const uint32_t sbase = smem_u32(smem);
    const int tid  = threadIdx.x;
    const int warp = tid >> 5;
    const int lane = tid & 31;
    const int wm = warp >> 1;             // 0..3
    const int wn = warp & 1;              // 0..1
    const int bm = blockIdx.y * GBM;
    const int bn = blockIdx.x * GBN;

    const __nv_bfloat16* Ah = ((MODE == 0) ? g_Xhi : g_Yhi) + (size_t)bm * KDIM;
    const __nv_bfloat16* Al = ((MODE == 0) ? g_Xlo : g_Ylo) + (size_t)bm * KDIM;
    const __nv_bfloat16* Bh = ((MODE == 0) ? g_WAhi : g_WPhi) + (size_t)bn * KDIM;
    const __nv_bfloat16* Bl = ((MODE == 0) ? g_WAlo : g_WPlo) + (size_t)bn * KDIM;

    const int arow = wm * 32 + (lane & 15);
    const int acb = (lane >> 4) & 1;
    const int brow = wn * 64 + (lane & 7) + ((lane & 16) >> 1);
    const int bcb = (lane >> 3) & 1;

    float acc[2][8][4];
#pragma unroll
    for (int mi = 0; mi < 2; mi++)
#pragma unroll
        for (int ni = 0; ni < 8; ni++)
#pragma unroll
            for (int r = 0; r < 4; r++) acc[mi][ni][r] = 0.0f;

#pragma unroll
    for (int t = 0; t < 2; t++) {
        load_tile_b(sbase + t * STAGE, Ah, Al, Bh, Bl, t * GBK, tid);
        CP_COMMIT();
    }

    for (int t = 0; t < KTILES; t++) {
        if (t < KTILES - 2)
            asm volatile("cp.async.wait_group 1;" ::: "memory");
        else
            asm volatile("cp.async.wait_group 0;" ::: "memory");
        __syncthreads();

        const uint32_t sg = sbase + (uint32_t)(t % 3) * STAGE;

#pragma unroll
        for (int ks = 0; ks < 2; ks++) {
            uint32_t ah[2][4], al[2][4], bh[4][4], bl[4][4];
#pragma unroll
            for (int mi = 0; mi < 2; mi++) {
                uint32_t ao = sw64(arow + mi * 16, ks * 2 + acb);
                ldsm_x4(ah[mi], sg + OAH + ao);
                ldsm_x4(al[mi], sg + OAL + ao);
            }
#pragma unroll
            for (int pi = 0; pi < 4; pi++) {
                uint32_t bo = sw64(brow + pi * 16, ks * 2 + bcb);
                ldsm_x4(bh[pi], sg + OBH + bo);
                ldsm_x4(bl[pi], sg + OBL + bo);
            }
#pragma unroll
            for (int mi = 0; mi < 2; mi++)
#pragma unroll
                for (int ni = 0; ni < 8; ni++) {
                    const int pi = ni >> 1;
                    const int j0 = (ni & 1) * 2;
                    mma_bf16(acc[mi][ni], al[mi], bh[pi][j0], bh[pi][j0 + 1]);
                    mma_bf16(acc[mi][ni], ah[mi], bl[pi][j0], bl[pi][j0 + 1]);
                    mma_bf16(acc[mi][ni], ah[mi], bh[pi][j0], bh[pi][j0 + 1]);
                }
        }

        if (t + 2 < KTILES) {
            load_tile_b(sbase + (uint32_t)((t + 2) % 3) * STAGE,
                        Ah, Al, Bh, Bl, (t + 2) * GBK, tid);
            CP_COMMIT();
        }
    }

    // Epilogue
#pragma unroll
    for (int mi = 0; mi < 2; mi++) {
#pragma unroll
        for (int ni = 0; ni < 8; ni++) {
            const int col = bn + wn * 64 + ni * 8 + (lane & 3) * 2;
            float2 bv = *(const float2*)(bias + col);
#pragma unroll
            for (int half = 0; half < 2; half++) {
                const int row = bm + wm * 32 + mi * 16 + (lane >> 2) + half * 8;
                float vx = acc[mi][ni][half * 2 + 0] + bv.x;
                float vy = acc[mi][ni][half * 2 + 1] + bv.y;
                if (MODE == 0) {
                    const int sec  = col >> 10;          // 0=q, 1=k, 2=v
                    const int cc   = col & 1023;
                    const int head = cc >> 6;
                    const int dpos = cc & 63;
                    const int b  = row >> 10;
                    const int tt = row & 1023;
                    const int bh2 = b * NH + head;
                    __nv_bfloat16 hx, lx, hy, ly;
                    bsplit(vx, hx, lx); bsplit(vy, hy, ly);
                    if (sec < 2) {
                        size_t o = ((size_t)bh2 * TSEQ + tt) * DH + dpos;
                        __nv_bfloat162 hv; hv.x = hx; hv.y = hy;
                        __nv_bfloat162 lv; lv.x = lx; lv.y = ly;
                        if (sec == 0) {
                            *(__nv_bfloat162*)(g_Qh + o) = hv;
                            *(__nv_bfloat162*)(g_Qlo + o) = lv;
                        } else {
                            *(__nv_bfloat162*)(g_Kh + o) = hv;
                            *(__nv_bfloat162*)(g_Klo + o) = lv;
                        }
                    } else {
                        size_t o0 = ((size_t)bh2 * DH + dpos) * TSEQ + tt;
                        g_Vth[o0] = hx; g_Vtl[o0] = lx;
                        g_Vth[o0 + TSEQ] = hy; g_Vtl[o0 + TSEQ] = ly;
                    }
                } else {
                    float2 v2; v2.x = vx; v2.y = vy;
                    *(float2*)(out + (size_t)row * N + col) = v2;
                }
            }
        }
    }
}

// ---------------------------------------------------------------------------
// Tensor-core flash attention, 3xBF16, FA2-style register-resident P
// (no P smem round trip) + double-buffered K/V tiles.
// smem: Q hi/lo 32KB + 2 x (K hi/lo + V^T hi/lo) 32KB = 96KB -> 2 CTAs/SM.
// ---------------------------------------------------------------------------
#define ABQ   128
#define ABK   64
#define SQH 0
#define SQL 16384
#define SKV 32768          // stage s at SKV + s*32768: {KH 0, KL 8K, VH 16K, VL 24K}
#define ASMEM 98304

__device__ __forceinline__ void attn_load_kv(uint32_t sbuf,
        const __nv_bfloat16* Khp, const __nv_bfloat16* Klp,
        const __nv_bfloat16* Vhp, const __nv_bfloat16* Vlp,
        int k0, int tid)
{
#pragma unroll
    for (int l = 0; l < 4; l++) {
        int idx = tid + l * 256;
        int panel = idx >> 9;            // 0 = hi, 1 = lo
        int rem = idx & 511;
        int r = rem >> 3, ch = rem & 7;
        uint32_t off = (uint32_t)r * 128 + ch * 16;
        uint32_t sw = off ^ ((off >> 3) & 0x70);
        cp_async16(sbuf + (panel ? 8192 : 0) + sw,
                   (panel ? Klp : Khp) + (size_t)(k0 + r) * DH + ch * 8);
        cp_async16(sbuf + (panel ? 24576 : 16384) + sw,
                   (panel ? Vlp : Vhp) + (size_t)r * TSEQ + k0 + ch * 8);
    }
}

__global__ __launch_bounds__(256, 2) void attn_kernel()
{
    extern __shared__ char smc[];
    const uint32_t sb = smem_u32(smc);

    const int qi = gridDim.x - 1 - blockIdx.x;   // heavy tiles first
    const int bh = blockIdx.y;
    const int bb = bh >> 4, hh = bh & 15;
    const __nv_bfloat16* Qhp = g_Qh  + (size_t)bh * TSEQ * DH;
    const __nv_bfloat16* Qlp = g_Qlo + (size_t)bh * TSEQ * DH;
    const __nv_bfloat16* Khp = g_Kh  + (size_t)bh * TSEQ * DH;
    const __nv_bfloat16* Klp = g_Klo + (size_t)bh * TSEQ * DH;
    const __nv_bfloat16* Vhp = g_Vth + (size_t)bh * DH * TSEQ;
    const __nv_bfloat16* Vlp = g_Vtl + (size_t)bh * DH * TSEQ;

    const int tid  = threadIdx.x;
    const int warp = tid >> 5;
    const int lane = tid & 31;
    const int rA   = lane >> 2;
    const int qcol = (lane & 3) * 2;

    const int acb  = (lane >> 4) & 1;
    const int bcb  = (lane >> 3) & 1;
    const int brow = (lane & 7) + ((lane & 16) >> 1);

    // Q panels (hi+lo): committed together with K/V tile 0
#pragma unroll
    for (int l = 0; l < 8; l++) {
        int idx = tid + l * 256;
        int panel = idx >> 10;
        int rem = idx & 1023;
        int r = rem >> 3, ch = rem & 7;
        uint32_t off = (uint32_t)r * 128 + ch * 16;
        uint32_t sw = off ^ ((off >> 3) & 0x70);
        const __nv_bfloat16* src = (panel ? Qlp : Qhp) + (size_t)(qi * ABQ + r) * DH + ch * 8;
        cp_async16(sb + (panel ? SQL : SQH) + sw, src);
    }
    attn_load_kv(sb + SKV, Khp, Klp, Vhp, Vlp, 0, tid);
    CP_COMMIT();

    float o[8][4];
#pragma unroll
    for (int ni = 0; ni < 8; ni++)
#pragma unroll
        for (int j = 0; j < 4; j++) o[ni][j] = 0.0f;
    float mA = -1e30f, mB = -1e30f, lAcc = 0.0f, lBcc = 0.0f;

    const float CS = 0.18033688011112042f;   // 0.125 * log2(e)
    const int ntiles = 2 * qi + 2;

    for (int kt = 0; kt < ntiles; kt++) {
        // prefetch next tile into the other buffer
        if (kt + 1 < ntiles) {
            attn_load_kv(sb + SKV + ((kt + 1) & 1) * 32768,
                         Khp, Klp, Vhp, Vlp, (kt + 1) * ABK, tid);
            CP_COMMIT();
            asm volatile("cp.async.wait_group 1;" ::: "memory");
        } else {
            asm volatile("cp.async.wait_group 0;" ::: "memory");
        }
        __syncthreads();

        const uint32_t skv = sb + SKV + (uint32_t)(kt & 1) * 32768;

        if (kt * ABK <= qi * ABQ + warp * 16 + 15) {
            // ---- S = Q K^T (3xbf16) ----
            float s[8][4];
#pragma unroll
            for (int ni = 0; ni < 8; ni++)
#pragma unroll
                for (int j = 0; j < 4; j++) s[ni][j] = 0.0f;

            const int aQrow = warp * 16 + (lane & 15);
            const uint32_t a_ro = (uint32_t)aQrow * 128;
            const int a_rx = aQrow & 7;
#pragma unroll
            for (int ks = 0; ks < 4; ks++) {
                uint32_t ah[4], al[4], kh[4][4], kl[4][4];
                uint32_t ao = a_ro + (uint32_t)(((ks * 2 + acb) ^ a_rx) << 4);
                ldsm_x4(ah, sb + SQH + ao);
                ldsm_x4(al, sb + SQL + ao);
#pragma unroll
                for (int pi = 0; pi < 4; pi++) {
                    int br = pi * 16 + brow;
                    uint32_t bo = (uint32_t)br * 128 +
                                  (uint32_t)(((ks * 2 + bcb) ^ (br & 7)) << 4);
                    ldsm_x4(kh[pi], skv + bo);           // K hi
                    ldsm_x4(kl[pi], skv + 8192 + bo);    // K lo
                }
#pragma unroll
                for (int ni = 0; ni < 8; ni++) {
                    const int pi = ni >> 1, j0 = (ni & 1) * 2;
                    mma_bf16(s[ni], al, kh[pi][j0], kh[pi][j0 + 1]);
                    mma_bf16(s[ni], ah, kl[pi][j0], kl[pi][j0 + 1]);
                    mma_bf16(s[ni], ah, kh[pi][j0], kh[pi][j0 + 1]);
                }
            }

            // ---- scale + causal mask ----
            const bool needmask = (kt * ABK + ABK - 1 > qi * ABQ + warp * 16);
            const int rowgA = qi * ABQ + warp * 16 + rA;
            const int rowgB = rowgA + 8;
            const int cb = kt * ABK + qcol;
#pragma unroll
            for (int ni = 0; ni < 8; ni++) {
                float z0 = s[ni][0] * CS, z1 = s[ni][1] * CS;
                float z2 = s[ni][2] * CS, z3 = s[ni][3] * CS;
                if (needmask) {
                    int c0 = cb + ni * 8, c1 = c0 + 1;
                    if (c0 > rowgA) z0 = -1e30f;
                    if (c1 > rowgA) z1 = -1e30f;
                    if (c0 > rowgB) z2 = -1e30f;
                    if (c1 > rowgB) z3 = -1e30f;
                }
                s[ni][0] = z0; s[ni][1] = z1; s[ni][2] = z2; s[ni][3] = z3;
            }

            // ---- online softmax ----
            float mtA = -1e30f, mtB = -1e30f;
#pragma unroll
            for (int ni = 0; ni < 8; ni++) {
                mtA = fmaxf(mtA, fmaxf(s[ni][0], s[ni][1]));
                mtB = fmaxf(mtB, fmaxf(s[ni][2], s[ni][3]));
            }
            mtA = fmaxf(mtA, __shfl_xor_sync(0xffffffffu, mtA, 1));
            mtA = fmaxf(mtA, __shfl_xor_sync(0xffffffffu, mtA, 2));
            mtB = fmaxf(mtB, __shfl_xor_sync(0xffffffffu, mtB, 1));
            mtB = fmaxf(mtB, __shfl_xor_sync(0xffffffffu, mtB, 2));

            const float mnA = fmaxf(mA, mtA);
            const float mnB = fmaxf(mB, mtB);
            const float aAl = fast_exp2(mA - mnA);
            const float aBl = fast_exp2(mB - mnB);
            mA = mnA; mB = mnB;

            float psA = 0.0f, psB = 0.0f;
#pragma unroll
            for (int ni = 0; ni < 8; ni++) {
                float p0 = fast_exp2(s[ni][0] - mnA);
                float p1 = fast_exp2(s[ni][1] - mnA);
                float p2 = fast_exp2(s[ni][2] - mnB);
                float p3 = fast_exp2(s[ni][3] - mnB);
                psA += p0 + p1; psB += p2 + p3;
                s[ni][0] = p0; s[ni][1] = p1; s[ni][2] = p2; s[ni][3] = p3;
            }
            psA += __shfl_xor_sync(0xffffffffu, psA, 1);
            psA += __shfl_xor_sync(0xffffffffu, psA, 2);
            psB += __shfl_xor_sync(0xffffffffu, psB, 1);
            psB += __shfl_xor_sync(0xffffffffu, psB, 2);
            lAcc = lAcc * aAl + psA;
            lBcc = lBcc * aBl + psB;

#pragma unroll
            for (int ni = 0; ni < 8; ni++) {
                o[ni][0] *= aAl; o[ni][1] *= aAl;
                o[ni][2] *= aBl; o[ni][3] *= aBl;
            }

            // ---- O += P V (3xbf16), P packed in registers (FA2 layout) ----
#pragma unroll
            for (int j = 0; j < 4; j++) {   // k-step over 16 keys
                uint32_t ph[4], pl[4];
#pragma unroll
                for (int half = 0; half < 2; half++) {   // kblk 0 / 8
                    const float* sp = s[2 * j + half];
                    __nv_bfloat162 h0 = __floats2bfloat162_rn(sp[0], sp[1]);  // row gr
                    __nv_bfloat162 h1 = __floats2bfloat162_rn(sp[2], sp[3]);  // row gr+8
                    __nv_bfloat162 l0 = __floats2bfloat162_rn(
                        sp[0] - __bfloat162float(h0.x), sp[1] - __bfloat162float(h0.y));
                    __nv_bfloat162 l1 = __floats2bfloat162_rn(
                        sp[2] - __bfloat162float(h1.x), sp[3] - __bfloat162float(h1.y));
                    ph[half * 2 + 0] = *(uint32_t*)&h0;
                    ph[half * 2 + 1] = *(uint32_t*)&h1;
                    pl[half * 2 + 0] = *(uint32_t*)&l0;
                    pl[half * 2 + 1] = *(uint32_t*)&l1;
                }
                // A fragment order: {row gr kblk0, row gr+8 kblk0, row gr kblk8, row gr+8 kblk8}
                uint32_t pa_h[4] = {ph[0], ph[1], ph[2], ph[3]};
                uint32_t pa_l[4] = {pl[0], pl[1], pl[2], pl[3]};

                uint32_t vh[4][4], vl[4][4];
#pragma unroll
                for (int pi = 0; pi < 4; pi++) {
                    int br = pi * 16 + brow;
                    uint32_t bo = (uint32_t)br * 128 +
                                  (uint32_t)(((j * 2 + bcb) ^ (br & 7)) << 4);
                    ldsm_x4(vh[pi], skv + 16384 + bo);   // V hi
                    ldsm_x4(vl[pi], skv + 24576 + bo);   // V lo
                }
#pragma unroll
                for (int ni = 0; ni < 8; ni++) {
                    const int pi = ni >> 1, j0 = (ni & 1) * 2;
                    mma_bf16(o[ni], pa_l, vh[pi][j0], vh[pi][j0 + 1]);
                    mma_bf16(o[ni], pa_h, vl[pi][j0], vl[pi][j0 + 1]);
                    mma_bf16(o[ni], pa_h, vh[pi][j0], vh[pi][j0 + 1]);
                }
            }
        }
        __syncthreads();   // all warps done with buf[kt&1] before its reload
    }

    // ---- epilogue: normalize, split to bf16, write g_Yhi/lo [b][t][c] ----
    const float invA = 1.0f / lAcc;
    const float invB = 1.0f / lBcc;
    const int tA = qi * ABQ + warp * 16 + rA;
    const int tB = tA + 8;
    const size_t baseA = ((size_t)bb * TSEQ + tA) * CDIM + hh * DH;
    const size_t baseB = ((size_t)bb * TSEQ + tB) * CDIM + hh * DH;
#pragma unroll
    for (int ni = 0; ni < 8; ni++) {
        int col = ni * 8 + qcol;
        float yA0 = o[ni][0] * invA, yA1 = o[ni][1] * invA;
        float yB0 = o[ni][2] * invB, yB1 = o[ni][3] * invB;
        __nv_bfloat16 h0, l0, h1, l1;
        __nv_bfloat162 hv, lv;
        bsplit(yA0, h0, l0); bsplit(yA1, h1, l1);
        hv.x = h0; hv.y = h1; lv.x = l0; lv.y = l1;
        *(__nv_bfloat162*)(g_Yhi + baseA + col) = hv;
        *(__nv_bfloat162*)(g_Ylo + baseA + col) = lv;
        bsplit(yB0, h0, l0); bsplit(yB1, h1, l1);
        hv.x = h0; hv.y = h1; lv.x = l0; lv.y = l1;
        *(__nv_bfloat162*)(g_Yhi + baseB + col) = hv;
        *(__nv_bfloat162*)(g_Ylo + baseB + col) = lv;
    }
}

// ---------------------------------------------------------------------------
// Launch
// ---------------------------------------------------------------------------
extern "C" void kernel_launch(void* const* d_in, const int* in_sizes, int n_in,
                              void* d_out, int out_size)
{
    const float* x      = (const float*)d_in[0];
    const float* w_attn = (const float*)d_in[1];
    const float* b_attn = (const float*)d_in[2];
    const float* w_proj = (const float*)d_in[3];
    const float* b_proj = (const float*)d_in[4];
    float* out = (float*)d_out;

    // 0) Transpose + split weights; split x
    {
        dim3 blk(32, 8);
        transpose_split_kernel<0><<<dim3(3 * CDIM / 32, KDIM / 32), blk>>>(w_attn, 3 * CDIM);
        transpose_split_kernel<1><<<dim3(CDIM / 32, KDIM / 32), blk>>>(w_proj, CDIM);
        split_kernel<<<(MROWS * KDIM) / (256 * 4), 256>>>(x);
    }

    // 1) QKV GEMM (3xbf16) -> pre-split Q/K + transposed V
    {
        cudaFuncSetAttribute(tc_gemm<3 * CDIM, 0>,
                             cudaFuncAttributeMaxDynamicSharedMemorySize, GSMEM);
        dim3 grid(3 * CDIM / GBN, MROWS / GBM);   // (24, 32)
        tc_gemm<3 * CDIM, 0><<<grid, 256, GSMEM>>>(b_attn, nullptr);
    }

    // 2) Tensor-core flash attention (3xbf16, FA2-style P, double-buffered K/V)
    {
        cudaFuncSetAttribute(attn_kernel,
                             cudaFuncAttributeMaxDynamicSharedMemorySize, ASMEM);
        dim3 grid(TSEQ / ABQ, NB * NH);           // (8, 64)
        attn_kernel<<<grid, 256, ASMEM>>>();
    }

    // 3) Output projection (3xbf16)
    {
        cudaFuncSetAttribute(tc_gemm<CDIM, 1>,
                             cudaFuncAttributeMaxDynamicSharedMemorySize, GSMEM);
        dim3 grid(CDIM / GBN, MROWS / GBM);       // (8, 32)
        tc_gemm<CDIM, 1><<<grid, 256, GSMEM>>>(b_proj, out);
    }
}